// round 1
// baseline (speedup 1.0000x reference)
#include <cuda_runtime.h>
#include <math.h>

#define BS   4096
#define L    20
#define NF   128
#define DM   640           // 3*NF + EF + TF
#define DIN  512           // DM - TF
#define DH   320           // DM / NHEAD
#define NB3  384           // NF+EF+TF

// ---------------- scratch (__device__ globals: allocation-free) ----------------
__device__ float s_full[BS*L*DM];        // gathered features (last row zeroed [:DIN])
__device__ float s_nb  [BS*L*NB3];       // [node_feat[hist], edge, ts]
__device__ float s_kv  [BS*L*2*DM];      // k (0:640) | v (640:1280)
__device__ float s_last[BS*DIN];         // last_event_feat (pre-zero)
__device__ float s_qlast[BS*DM];
__device__ float s_ctx [BS*DM];
__device__ float s_mha [BS*DM];
__device__ float s_qn  [BS*NF];
__device__ float s_qh  [BS*NF];
__device__ float s_kh  [BS*L*NF];
__device__ float s_vh  [BS*L*NF];
__device__ float s_mrg [BS*2*NF];
__device__ float s_hpl [BS*NF];
__device__ float s_gi  [BS*3*NF];
__device__ float s_gh  [BS*3*NF];
__device__ float s_hpr [BS*NF];

// ---------------- generic fp32 GEMM: C = A @ B(^T) + bias, optional tanh ----------------
// A: (M,K) rows at stride lda. BT=1: B is (N,K) row-major (use B^T). BT=0: B is (K,N).
// Tiles 64x64x16, 256 threads, 4x4 per thread. Requires M%64==0, N%64==0, K%16==0.
template<int BT, int ACT>
__global__ __launch_bounds__(256) void gemm_k(
    const float* __restrict__ A, int lda,
    const float* __restrict__ B,
    const float* __restrict__ bias,
    float* __restrict__ C,
    int M, int N, int K)
{
    __shared__ float As[16][64];
    __shared__ float Bs[16][64];
    const int bm = blockIdx.y * 64;
    const int bn = blockIdx.x * 64;
    const int t  = threadIdx.x;
    const int tx = t & 15, ty = t >> 4;
    const int ar = t >> 2, ac = (t & 3) << 2;     // A/BT loads: row 0..63, col group
    const int br = t >> 4, bc = (t & 15) << 2;    // non-BT loads: row 0..15, col 0..60
    float acc[4][4] = {};
    for (int k0 = 0; k0 < K; k0 += 16) {
        float4 av = *(const float4*)(A + (size_t)(bm + ar) * lda + k0 + ac);
        As[ac+0][ar] = av.x; As[ac+1][ar] = av.y; As[ac+2][ar] = av.z; As[ac+3][ar] = av.w;
        if (BT) {
            float4 bv = *(const float4*)(B + (size_t)(bn + ar) * K + k0 + ac);
            Bs[ac+0][ar] = bv.x; Bs[ac+1][ar] = bv.y; Bs[ac+2][ar] = bv.z; Bs[ac+3][ar] = bv.w;
        } else {
            float4 bv = *(const float4*)(B + (size_t)(k0 + br) * N + bn + bc);
            *(float4*)(&Bs[br][bc]) = bv;
        }
        __syncthreads();
        #pragma unroll
        for (int kk = 0; kk < 16; kk++) {
            float4 a4 = *(const float4*)(&As[kk][ty << 2]);
            float4 b4 = *(const float4*)(&Bs[kk][tx << 2]);
            float a[4] = {a4.x, a4.y, a4.z, a4.w};
            float b[4] = {b4.x, b4.y, b4.z, b4.w};
            #pragma unroll
            for (int i = 0; i < 4; i++)
                #pragma unroll
                for (int j = 0; j < 4; j++)
                    acc[i][j] += a[i] * b[j];
        }
        __syncthreads();
    }
    #pragma unroll
    for (int i = 0; i < 4; i++) {
        float4 o;
        float* op = &o.x;
        #pragma unroll
        for (int j = 0; j < 4; j++) {
            float v = acc[i][j];
            if (bias) v += bias[bn + (tx << 2) + j];
            if (ACT == 1) v = tanhf(v);
            op[j] = v;
        }
        *(float4*)(C + (size_t)(bm + (ty << 2) + i) * N + bn + (tx << 2)) = o;
    }
}

// ---------------- gather + feature build ----------------
__global__ __launch_bounds__(128) void build_kernel(
    const int* __restrict__ nids, const int* __restrict__ hist_nids,
    const int* __restrict__ anon_ids, const int* __restrict__ hist_eids,
    const float* __restrict__ hist_ts, const int* __restrict__ hist_dirs,
    const float* __restrict__ node_feat, const float* __restrict__ edge_feat,
    const float* __restrict__ anony_emb, const float* __restrict__ time_w,
    const float* __restrict__ time_b,
    float* __restrict__ full, float* __restrict__ nb, float* __restrict__ last)
{
    int bl = blockIdx.x;            // b*L + l
    int b = bl / L, l = bl % L;
    int f = threadIdx.x;            // 0..127
    int nid = nids[b];
    int hn  = hist_nids[bl];
    int dir = hist_dirs[bl];
    int src = dir ? nid : hn;
    int dst = dir ? hn  : nid;
    int eid = hist_eids[bl];
    int aid = anon_ids[bl];
    float dt = hist_ts[b*L + L-1] - hist_ts[bl];
    float sv = node_feat[(size_t)src*NF + f];
    float dv = node_feat[(size_t)dst*NF + f];
    float av = anony_emb[(size_t)aid*NF + f];
    float ev = edge_feat[(size_t)eid*NF + f];
    float tv = cosf(dt * time_w[f] + time_b[f]);
    float hv = node_feat[(size_t)hn*NF + f];
    size_t fb  = (size_t)bl * DM;
    size_t nbb = (size_t)bl * NB3;
    if (l == L-1) {
        size_t lb = (size_t)b * DIN;
        last[lb + f]      = sv;
        last[lb + NF + f] = dv;
        last[lb + 2*NF+f] = av;
        last[lb + 3*NF+f] = ev;
        full[fb + f] = 0.f; full[fb + NF + f] = 0.f;
        full[fb + 2*NF + f] = 0.f; full[fb + 3*NF + f] = 0.f;
    } else {
        full[fb + f] = sv; full[fb + NF + f] = dv;
        full[fb + 2*NF + f] = av; full[fb + 3*NF + f] = ev;
    }
    full[fb + 4*NF + f] = tv;
    nb[nbb + f] = hv; nb[nbb + NF + f] = ev; nb[nbb + 2*NF + f] = tv;
}

// ---------------- MHA at last query position only ----------------
__global__ __launch_bounds__(256) void mha_kernel(
    const float* __restrict__ qlast, const float* __restrict__ kv,
    const int* __restrict__ hist_nids, float* __restrict__ ctx)
{
    int b = blockIdx.x;
    __shared__ float qs[DM];
    __shared__ float sc[2*L];
    int t = threadIdx.x;
    for (int d = t; d < DM; d += 256) qs[d] = qlast[(size_t)b*DM + d];
    __syncthreads();
    int w = t >> 5, lane = t & 31;
    for (int p = w; p < 2*L; p += 8) {
        int h = p / L, m = p % L;
        const float* kp = kv + (size_t)(b*L + m)*(2*DM) + h*DH;
        const float* qp = qs + h*DH;
        float s = 0.f;
        for (int d = lane; d < DH; d += 32) s += qp[d] * kp[d];
        #pragma unroll
        for (int o = 16; o; o >>= 1) s += __shfl_xor_sync(0xffffffffu, s, o);
        if (lane == 0) {
            bool msk = (hist_nids[b*L + m] == 0) && (m != L-1);
            sc[p] = msk ? -1e9f : s * (1.f / sqrtf((float)DH));
        }
    }
    __syncthreads();
    if (t < 2) {
        float mx = -1e30f;
        for (int m = 0; m < L; m++) mx = fmaxf(mx, sc[t*L + m]);
        float sum = 0.f;
        for (int m = 0; m < L; m++) { float e = expf(sc[t*L + m] - mx); sc[t*L + m] = e; sum += e; }
        float inv = 1.f / sum;
        for (int m = 0; m < L; m++) sc[t*L + m] *= inv;
    }
    __syncthreads();
    for (int d = t; d < DM; d += 256) {
        int h = d / DH, dd = d - h*DH;
        const float* vp = kv + (size_t)(b*L)*(2*DM) + DM + h*DH + dd;
        float acc = 0.f;
        #pragma unroll
        for (int m = 0; m < L; m++) acc += sc[h*L + m] * vp[(size_t)m*(2*DM)];
        ctx[(size_t)b*DM + d] = acc;
    }
}

// ---------------- pooling attention + merge-input build ----------------
__global__ __launch_bounds__(128) void attn2_kernel(
    const float* __restrict__ qh, const float* __restrict__ kh,
    const float* __restrict__ vh, const int* __restrict__ hist_nids,
    const int* __restrict__ nids, const float* __restrict__ node_feat,
    float* __restrict__ mergein)
{
    int b = blockIdx.x, t = threadIdx.x;
    __shared__ float q[NF];
    __shared__ float a[L];
    q[t] = qh[(size_t)b*NF + t];
    __syncthreads();
    int w = t >> 5, lane = t & 31;
    for (int l = w; l < L; l += 4) {
        const float* kp = kh + (size_t)(b*L + l)*NF;
        float s = 0.f;
        #pragma unroll
        for (int d = lane; d < NF; d += 32) s += q[d] * kp[d];
        #pragma unroll
        for (int o = 16; o; o >>= 1) s += __shfl_xor_sync(0xffffffffu, s, o);
        if (lane == 0) {
            bool msk = (hist_nids[b*L + l] == 0) && (l != L-1);
            a[l] = msk ? -1e9f : s * (1.f / sqrtf((float)NF));
        }
    }
    __syncthreads();
    if (t == 0) {
        float mx = -1e30f;
        for (int l = 0; l < L; l++) mx = fmaxf(mx, a[l]);
        float sum = 0.f;
        for (int l = 0; l < L; l++) { float e = expf(a[l] - mx); a[l] = e; sum += e; }
        float inv = 1.f / sum;
        for (int l = 0; l < L; l++) a[l] *= inv;
    }
    __syncthreads();
    float acc = 0.f;
    #pragma unroll
    for (int l = 0; l < L; l++) acc += a[l] * vh[(size_t)(b*L + l)*NF + t];
    mergein[(size_t)b*2*NF + t]      = acc;
    mergein[(size_t)b*2*NF + NF + t] = node_feat[(size_t)nids[b]*NF + t];
}

// ---------------- GRU cell elementwise ----------------
__global__ void gru_kernel(const float* __restrict__ gi, const float* __restrict__ gh,
                           const float* __restrict__ hpl, float* __restrict__ hpr)
{
    int idx = blockIdx.x * blockDim.x + threadIdx.x;
    if (idx >= BS*NF) return;
    int b = idx / NF, f = idx - b*NF;
    const float* gib = gi + (size_t)b*3*NF;
    const float* ghb = gh + (size_t)b*3*NF;
    float r = 1.f / (1.f + expf(-(gib[f]        + ghb[f])));
    float z = 1.f / (1.f + expf(-(gib[NF + f]   + ghb[NF + f])));
    float n = tanhf(gib[2*NF + f] + r * ghb[2*NF + f]);
    hpr[idx] = (1.f - z) * n + z * hpl[idx];
}

// ---------------- RK4 ODE integrator (one row per block) ----------------
// NOTE: invalid_rows in the reference is provably all-False (mask[:,-1] forced
// False before all()), so no output masking is applied.
#define ODE_SMEM ((128*129 + 128) * 4)
__global__ __launch_bounds__(128) void ode_kernel(
    const float* __restrict__ hpr, const float* __restrict__ ode_w,
    const float* __restrict__ ode_b, const float* __restrict__ tnode_w,
    const float* __restrict__ tnode_b, const float* __restrict__ hist_ts,
    float* __restrict__ out)
{
    extern __shared__ float sm[];
    float* Ws = sm;                 // [128][129] padded: Ws[f*129 + k] = ode_w[f][k]
    float* vs = sm + 128*129;       // shared eval input (128)
    int b = blockIdx.x, f = threadIdx.x;
    for (int i = f; i < NF*NF; i += 128) Ws[(i >> 7)*129 + (i & 127)] = ode_w[i];
    float t0 = hist_ts[b*L + L-2];
    float t1 = hist_ts[b*L + L-1];
    float ratio = t1 - t0;
    float twf = tnode_w[f], tbf = tnode_b[f], obf = ode_b[f];
    float h0 = hpr[(size_t)b*NF + f];
    float z = h0;
    __syncthreads();

    auto feval = [&](float s, float zin) -> float {
        float t = s * ratio + t0;
        vs[f] = zin + cosf(t * twf + tbf);
        __syncthreads();
        float acc = obf;
        const float* wr = Ws + f*129;
        #pragma unroll 8
        for (int k = 0; k < NF; k++) acc += vs[k] * wr[k];
        __syncthreads();
        return tanhf(acc) * ratio;
    };

    const float ds = 0.125f;
    for (int st = 0; st < 8; st++) {
        float s = st * ds;
        float k1 = feval(s,            z);
        float k2 = feval(s + 0.5f*ds,  z + 0.5f*ds*k1);
        float k3 = feval(s + 0.5f*ds,  z + 0.5f*ds*k2);
        float k4 = feval(s + ds,       z + ds*k3);
        z += ds * (1.f/6.f) * (k1 + 2.f*k2 + 2.f*k3 + k4);
    }
    out[(size_t)b*NF + f] = z;                              // h_left
    out[(size_t)BS*NF + (size_t)b*NF + f] = h0;             // h_right
    if (f == 0) out[(size_t)2*BS*NF + b] = t1;              // hist_ts[:, -1]
}

// ---------------- launch ----------------
extern "C" void kernel_launch(void* const* d_in, const int* in_sizes, int n_in,
                              void* d_out, int out_size)
{
    const int*   nids      = (const int*)  d_in[0];
    // d_in[1] = ts (unused by reference)
    const int*   hist_nids = (const int*)  d_in[2];
    const int*   anon      = (const int*)  d_in[3];
    const int*   eids      = (const int*)  d_in[4];
    const float* hist_ts   = (const float*)d_in[5];
    const int*   dirs      = (const int*)  d_in[6];
    const float* node_feat = (const float*)d_in[7];
    const float* edge_feat = (const float*)d_in[8];
    const float* anony_emb = (const float*)d_in[9];
    const float* time_w    = (const float*)d_in[10];
    const float* time_b    = (const float*)d_in[11];
    const float* in_proj_w = (const float*)d_in[12];
    const float* in_proj_b = (const float*)d_in[13];
    const float* out_proj_w= (const float*)d_in[14];
    const float* out_proj_b= (const float*)d_in[15];
    const float* outfn_w   = (const float*)d_in[16];
    const float* outfn_b   = (const float*)d_in[17];
    const float* attn_wq   = (const float*)d_in[18];
    const float* attn_wk   = (const float*)d_in[19];
    const float* attn_wv   = (const float*)d_in[20];
    const float* merge_w   = (const float*)d_in[21];
    const float* merge_b   = (const float*)d_in[22];
    const float* gru_w_ih  = (const float*)d_in[23];
    const float* gru_w_hh  = (const float*)d_in[24];
    const float* gru_b_ih  = (const float*)d_in[25];
    const float* gru_b_hh  = (const float*)d_in[26];
    const float* ode_w     = (const float*)d_in[27];
    const float* ode_b     = (const float*)d_in[28];
    const float* tnode_w   = (const float*)d_in[29];
    const float* tnode_b   = (const float*)d_in[30];
    float* out = (float*)d_out;

    float *p_full, *p_nb, *p_kv, *p_last, *p_qlast, *p_ctx, *p_mha, *p_qn,
          *p_qh, *p_kh, *p_vh, *p_mrg, *p_hpl, *p_gi, *p_gh, *p_hpr;
    cudaGetSymbolAddress((void**)&p_full,  s_full);
    cudaGetSymbolAddress((void**)&p_nb,    s_nb);
    cudaGetSymbolAddress((void**)&p_kv,    s_kv);
    cudaGetSymbolAddress((void**)&p_last,  s_last);
    cudaGetSymbolAddress((void**)&p_qlast, s_qlast);
    cudaGetSymbolAddress((void**)&p_ctx,   s_ctx);
    cudaGetSymbolAddress((void**)&p_mha,   s_mha);
    cudaGetSymbolAddress((void**)&p_qn,    s_qn);
    cudaGetSymbolAddress((void**)&p_qh,    s_qh);
    cudaGetSymbolAddress((void**)&p_kh,    s_kh);
    cudaGetSymbolAddress((void**)&p_vh,    s_vh);
    cudaGetSymbolAddress((void**)&p_mrg,   s_mrg);
    cudaGetSymbolAddress((void**)&p_hpl,   s_hpl);
    cudaGetSymbolAddress((void**)&p_gi,    s_gi);
    cudaGetSymbolAddress((void**)&p_gh,    s_gh);
    cudaGetSymbolAddress((void**)&p_hpr,   s_hpr);

    // 1. gather/build
    build_kernel<<<BS*L, 128>>>(nids, hist_nids, anon, eids, hist_ts, dirs,
                                node_feat, edge_feat, anony_emb, time_w, time_b,
                                p_full, p_nb, p_last);

    // 2. K,V projection for all positions (rows DM..3DM of in_proj_w)
    gemm_k<1,0><<<dim3(2*DM/64, BS*L/64), 256>>>(p_full, DM, in_proj_w + (size_t)DM*DM,
                                                 in_proj_b + DM, p_kv, BS*L, 2*DM, DM);
    // 3. Q projection only at last position (strided A)
    gemm_k<1,0><<<dim3(DM/64, BS/64), 256>>>(p_full + (size_t)(L-1)*DM, L*DM, in_proj_w,
                                             in_proj_b, p_qlast, BS, DM, DM);
    // 4. attention (last query row)
    mha_kernel<<<BS, 256>>>(p_qlast, p_kv, hist_nids, p_ctx);
    // 5. out_proj, outfn
    gemm_k<1,0><<<dim3(DM/64, BS/64), 256>>>(p_ctx, DM, out_proj_w, out_proj_b, p_mha, BS, DM, DM);
    gemm_k<1,0><<<dim3(NF/64, BS/64), 256>>>(p_mha, DM, outfn_w, outfn_b, p_qn, BS, NF, DM);
    // 6. pooling attention projections
    gemm_k<0,0><<<dim3(NF/64, BS/64), 256>>>(p_qn, NF, attn_wq, nullptr, p_qh, BS, NF, NF);
    gemm_k<0,0><<<dim3(NF/64, BS*L/64), 256>>>(p_nb, NB3, attn_wk, nullptr, p_kh, BS*L, NF, NB3);
    gemm_k<0,0><<<dim3(NF/64, BS*L/64), 256>>>(p_nb, NB3, attn_wv, nullptr, p_vh, BS*L, NF, NB3);
    attn2_kernel<<<BS, 128>>>(p_qh, p_kh, p_vh, hist_nids, nids, node_feat, p_mrg);
    // 7. merge (tanh epilogue)
    gemm_k<0,1><<<dim3(NF/64, BS/64), 256>>>(p_mrg, 2*NF, merge_w, merge_b, p_hpl, BS, NF, 2*NF);
    // 8. GRU
    gemm_k<1,0><<<dim3(3*NF/64, BS/64), 256>>>(p_last, DIN, gru_w_ih, gru_b_ih, p_gi, BS, 3*NF, DIN);
    gemm_k<1,0><<<dim3(3*NF/64, BS/64), 256>>>(p_hpl, NF, gru_w_hh, gru_b_hh, p_gh, BS, 3*NF, NF);
    gru_kernel<<<(BS*NF + 255)/256, 256>>>(p_gi, p_gh, p_hpl, p_hpr);
    // 9. RK4 ODE + final outputs
    cudaFuncSetAttribute(ode_kernel, cudaFuncAttributeMaxDynamicSharedMemorySize, ODE_SMEM);
    ode_kernel<<<BS, 128, ODE_SMEM>>>(p_hpr, ode_w, ode_b, tnode_w, tnode_b, hist_ts, out);
}

// round 2
// speedup vs baseline: 2.0444x; 2.0444x over previous
#include <cuda_runtime.h>
#include <math.h>

#define BS   4096
#define L    20
#define NF   128
#define DM   640           // 3*NF + EF + TF
#define DIN  512           // DM - TF
#define DH   320           // DM / NHEAD
#define NB3  384           // NF+EF+TF

// ---------------- scratch (__device__ globals: allocation-free) ----------------
__device__ float s_full[BS*L*DM];
__device__ float s_nb  [BS*L*NB3];
__device__ float s_kv  [BS*L*2*DM];
__device__ float s_last[BS*DIN];
__device__ float s_qlast[BS*DM];
__device__ float s_ctx [BS*DM];
__device__ float s_mha [BS*DM];
__device__ float s_qn  [BS*NF];
__device__ float s_qh  [BS*NF];
__device__ float s_kh  [BS*L*NF];
__device__ float s_vh  [BS*L*NF];
__device__ float s_mrg [BS*2*NF];
__device__ float s_hpl [BS*NF];
__device__ float s_gi  [BS*3*NF];
__device__ float s_gh  [BS*3*NF];
__device__ float s_hpr [BS*NF];

__device__ __forceinline__ unsigned f2tf(float v) {
    unsigned r;
    asm("cvt.rna.tf32.f32 %0, %1;" : "=r"(r) : "f"(v));
    return r;
}

__device__ __forceinline__ void mma_tf32(float c[4], unsigned a0, unsigned a1,
                                         unsigned a2, unsigned a3,
                                         unsigned b0, unsigned b1) {
    asm volatile(
        "mma.sync.aligned.m16n8k8.row.col.f32.tf32.tf32.f32 "
        "{%0,%1,%2,%3}, {%4,%5,%6,%7}, {%8,%9}, {%0,%1,%2,%3};"
        : "+f"(c[0]), "+f"(c[1]), "+f"(c[2]), "+f"(c[3])
        : "r"(a0), "r"(a1), "r"(a2), "r"(a3), "r"(b0), "r"(b1));
}

// ---------------- tf32 tensor-core GEMM ----------------
// C(M,N) = A(M,K; row stride lda) @ B + bias, optional tanh.
// BT=1: B is (N,K) row-major (compute A@B^T). BT=0: B is (K,N) row-major.
// Block 128x128x16, 256 threads (8 warps), warp tile 64x32 (m16n8k8 frags).
// Requires M%128==0, N%128==0, K%16==0.
template<int BT, int ACT>
__global__ __launch_bounds__(256) void gemm_tc(
    const float* __restrict__ A, int lda,
    const float* __restrict__ B,
    const float* __restrict__ bias,
    float* __restrict__ C,
    int M, int N, int K)
{
    __shared__ __align__(16) unsigned As[2048];  // packed frags: ((s*8+im)*32+lane)*4+reg
    __shared__ __align__(16) unsigned Bs[2048];  // packed frags: ((s*16+jn)*32+lane)*2+reg
    const int bm = blockIdx.y * 128;
    const int bn = blockIdx.x * 128;
    const int t  = threadIdx.x;
    const int lane = t & 31;
    const int wr = (t >> 5) >> 2;   // 0..1
    const int wc = (t >> 5) & 3;    // 0..3

    // A staging: thread handles rows (ma, ma+64), k-offset ca*4..+3
    const int ma = t >> 2, ca = t & 3;
    const float* Ag = A + (size_t)(bm + ma) * lda + ca * 4;
    // B staging
    const float* Bg;
    int kb = 0, nb4 = 0, nbr = 0, cb = 0;
    if (BT) { nbr = t >> 2; cb = t & 3; Bg = B + (size_t)(bn + nbr) * K + cb * 4; }
    else    { kb = t >> 5; nb4 = t & 31; Bg = B + (size_t)kb * N + bn + nb4 * 4; }

    float4 ra0, ra1, rb0, rb1;
    auto ldg = [&]() {
        ra0 = *(const float4*)Ag;
        ra1 = *(const float4*)(Ag + (size_t)64 * lda);
        Ag += 16;
        if (BT) {
            rb0 = *(const float4*)Bg;
            rb1 = *(const float4*)(Bg + (size_t)64 * K);
            Bg += 16;
        } else {
            rb0 = *(const float4*)Bg;
            rb1 = *(const float4*)(Bg + (size_t)8 * N);
            Bg += (size_t)16 * N;
        }
    };

    // A STS constants
    const int imA = ma >> 4, rA = ma & 15, gA = rA & 7, hiA = rA >> 3;
    const int sA = ca >> 1, k2A = ca & 1;
    const int baseA0 = (((sA * 8 + imA)     * 32 + gA * 4) * 4) + k2A * 2 + hiA;
    const int baseA1 = (((sA * 8 + imA + 4) * 32 + gA * 4) * 4) + k2A * 2 + hiA;

    auto sts = [&]() {
        const float* v0 = &ra0.x; const float* v1 = &ra1.x;
        #pragma unroll
        for (int j = 0; j < 4; j++) {
            As[baseA0 + 4*j] = f2tf(v0[j]);
            As[baseA1 + 4*j] = f2tf(v1[j]);
        }
        if (BT) {
            const int g = nbr & 7, jn0 = (nbr >> 3), jn1 = jn0 + 8;
            const int sB = cb >> 1, regB = cb & 1;
            const int b0 = ((sB * 16 + jn0) * 32 + g * 4) * 2 + regB;
            const int b1 = ((sB * 16 + jn1) * 32 + g * 4) * 2 + regB;
            const float* w0 = &rb0.x; const float* w1 = &rb1.x;
            #pragma unroll
            for (int j = 0; j < 4; j++) {
                Bs[b0 + 2*j] = f2tf(w0[j]);
                Bs[b1 + 2*j] = f2tf(w1[j]);
            }
        } else {
            const int jn = nb4 >> 1, gb = (nb4 & 1) * 4;
            const int tig = kb & 3, regB = (kb >> 2) & 1;
            const int b0 = ((0 * 16 + jn) * 32 + gb * 4 + tig) * 2 + regB;
            const int b1 = ((1 * 16 + jn) * 32 + gb * 4 + tig) * 2 + regB;
            const float* w0 = &rb0.x; const float* w1 = &rb1.x;
            #pragma unroll
            for (int j = 0; j < 4; j++) {
                Bs[b0 + 8*j] = f2tf(w0[j]);
                Bs[b1 + 8*j] = f2tf(w1[j]);
            }
        }
    };

    float acc[4][4][4] = {};
    const int niter = K >> 4;
    ldg();
    for (int it = 0; it < niter; it++) {
        sts();
        __syncthreads();
        if (it + 1 < niter) ldg();
        #pragma unroll
        for (int s = 0; s < 2; s++) {
            uint4 af[4]; uint2 bf[4];
            #pragma unroll
            for (int i = 0; i < 4; i++)
                af[i] = *(const uint4*)&As[((s*8 + wr*4 + i) * 32 + lane) * 4];
            #pragma unroll
            for (int j = 0; j < 4; j++)
                bf[j] = *(const uint2*)&Bs[((s*16 + wc*4 + j) * 32 + lane) * 2];
            #pragma unroll
            for (int i = 0; i < 4; i++)
                #pragma unroll
                for (int j = 0; j < 4; j++)
                    mma_tf32(acc[i][j], af[i].x, af[i].y, af[i].z, af[i].w,
                             bf[j].x, bf[j].y);
        }
        __syncthreads();
    }

    // epilogue
    const int g = lane >> 2, tig = lane & 3;
    #pragma unroll
    for (int i = 0; i < 4; i++) {
        int row = bm + wr * 64 + i * 16 + g;
        #pragma unroll
        for (int j = 0; j < 4; j++) {
            int col = bn + wc * 32 + j * 8 + tig * 2;
            float b0 = bias ? bias[col] : 0.f;
            float b1 = bias ? bias[col + 1] : 0.f;
            float v00 = acc[i][j][0] + b0, v01 = acc[i][j][1] + b1;
            float v10 = acc[i][j][2] + b0, v11 = acc[i][j][3] + b1;
            if (ACT == 1) { v00 = tanhf(v00); v01 = tanhf(v01);
                            v10 = tanhf(v10); v11 = tanhf(v11); }
            *(float2*)(C + (size_t)row * N + col)       = make_float2(v00, v01);
            *(float2*)(C + (size_t)(row + 8) * N + col) = make_float2(v10, v11);
        }
    }
}

// ---------------- gather + feature build ----------------
__global__ __launch_bounds__(128) void build_kernel(
    const int* __restrict__ nids, const int* __restrict__ hist_nids,
    const int* __restrict__ anon_ids, const int* __restrict__ hist_eids,
    const float* __restrict__ hist_ts, const int* __restrict__ hist_dirs,
    const float* __restrict__ node_feat, const float* __restrict__ edge_feat,
    const float* __restrict__ anony_emb, const float* __restrict__ time_w,
    const float* __restrict__ time_b,
    float* __restrict__ full, float* __restrict__ nb, float* __restrict__ last)
{
    int bl = blockIdx.x;
    int b = bl / L, l = bl % L;
    int f = threadIdx.x;
    int nid = nids[b];
    int hn  = hist_nids[bl];
    int dir = hist_dirs[bl];
    int src = dir ? nid : hn;
    int dst = dir ? hn  : nid;
    int eid = hist_eids[bl];
    int aid = anon_ids[bl];
    float dt = hist_ts[b*L + L-1] - hist_ts[bl];
    float sv = node_feat[(size_t)src*NF + f];
    float dv = node_feat[(size_t)dst*NF + f];
    float av = anony_emb[(size_t)aid*NF + f];
    float ev = edge_feat[(size_t)eid*NF + f];
    float tv = cosf(dt * time_w[f] + time_b[f]);
    float hv = node_feat[(size_t)hn*NF + f];
    size_t fb  = (size_t)bl * DM;
    size_t nbb = (size_t)bl * NB3;
    if (l == L-1) {
        size_t lb = (size_t)b * DIN;
        last[lb + f]      = sv;
        last[lb + NF + f] = dv;
        last[lb + 2*NF+f] = av;
        last[lb + 3*NF+f] = ev;
        full[fb + f] = 0.f; full[fb + NF + f] = 0.f;
        full[fb + 2*NF + f] = 0.f; full[fb + 3*NF + f] = 0.f;
    } else {
        full[fb + f] = sv; full[fb + NF + f] = dv;
        full[fb + 2*NF + f] = av; full[fb + 3*NF + f] = ev;
    }
    full[fb + 4*NF + f] = tv;
    nb[nbb + f] = hv; nb[nbb + NF + f] = ev; nb[nbb + 2*NF + f] = tv;
}

// ---------------- MHA at last query position only ----------------
__global__ __launch_bounds__(256) void mha_kernel(
    const float* __restrict__ qlast, const float* __restrict__ kv,
    const int* __restrict__ hist_nids, float* __restrict__ ctx)
{
    int b = blockIdx.x;
    __shared__ float qs[DM];
    __shared__ float sc[2*L];
    int t = threadIdx.x;
    for (int d = t; d < DM; d += 256) qs[d] = qlast[(size_t)b*DM + d];
    __syncthreads();
    int w = t >> 5, lane = t & 31;
    for (int p = w; p < 2*L; p += 8) {
        int h = p / L, m = p % L;
        const float* kp = kv + (size_t)(b*L + m)*(2*DM) + h*DH;
        const float* qp = qs + h*DH;
        float s = 0.f;
        for (int d = lane; d < DH; d += 32) s += qp[d] * kp[d];
        #pragma unroll
        for (int o = 16; o; o >>= 1) s += __shfl_xor_sync(0xffffffffu, s, o);
        if (lane == 0) {
            bool msk = (hist_nids[b*L + m] == 0) && (m != L-1);
            sc[p] = msk ? -1e9f : s * (1.f / sqrtf((float)DH));
        }
    }
    __syncthreads();
    if (t < 2) {
        float mx = -1e30f;
        for (int m = 0; m < L; m++) mx = fmaxf(mx, sc[t*L + m]);
        float sum = 0.f;
        for (int m = 0; m < L; m++) { float e = expf(sc[t*L + m] - mx); sc[t*L + m] = e; sum += e; }
        float inv = 1.f / sum;
        for (int m = 0; m < L; m++) sc[t*L + m] *= inv;
    }
    __syncthreads();
    for (int d = t; d < DM; d += 256) {
        int h = d / DH, dd = d - h*DH;
        const float* vp = kv + (size_t)(b*L)*(2*DM) + DM + h*DH + dd;
        float acc = 0.f;
        #pragma unroll
        for (int m = 0; m < L; m++) acc += sc[h*L + m] * vp[(size_t)m*(2*DM)];
        ctx[(size_t)b*DM + d] = acc;
    }
}

// ---------------- pooling attention + merge-input build ----------------
__global__ __launch_bounds__(128) void attn2_kernel(
    const float* __restrict__ qh, const float* __restrict__ kh,
    const float* __restrict__ vh, const int* __restrict__ hist_nids,
    const int* __restrict__ nids, const float* __restrict__ node_feat,
    float* __restrict__ mergein)
{
    int b = blockIdx.x, t = threadIdx.x;
    __shared__ float q[NF];
    __shared__ float a[L];
    q[t] = qh[(size_t)b*NF + t];
    __syncthreads();
    int w = t >> 5, lane = t & 31;
    for (int l = w; l < L; l += 4) {
        const float* kp = kh + (size_t)(b*L + l)*NF;
        float s = 0.f;
        #pragma unroll
        for (int d = lane; d < NF; d += 32) s += q[d] * kp[d];
        #pragma unroll
        for (int o = 16; o; o >>= 1) s += __shfl_xor_sync(0xffffffffu, s, o);
        if (lane == 0) {
            bool msk = (hist_nids[b*L + l] == 0) && (l != L-1);
            a[l] = msk ? -1e9f : s * (1.f / sqrtf((float)NF));
        }
    }
    __syncthreads();
    if (t == 0) {
        float mx = -1e30f;
        for (int l = 0; l < L; l++) mx = fmaxf(mx, a[l]);
        float sum = 0.f;
        for (int l = 0; l < L; l++) { float e = expf(a[l] - mx); a[l] = e; sum += e; }
        float inv = 1.f / sum;
        for (int l = 0; l < L; l++) a[l] *= inv;
    }
    __syncthreads();
    float acc = 0.f;
    #pragma unroll
    for (int l = 0; l < L; l++) acc += a[l] * vh[(size_t)(b*L + l)*NF + t];
    mergein[(size_t)b*2*NF + t]      = acc;
    mergein[(size_t)b*2*NF + NF + t] = node_feat[(size_t)nids[b]*NF + t];
}

// ---------------- GRU cell elementwise ----------------
__global__ void gru_kernel(const float* __restrict__ gi, const float* __restrict__ gh,
                           const float* __restrict__ hpl, float* __restrict__ hpr)
{
    int idx = blockIdx.x * blockDim.x + threadIdx.x;
    if (idx >= BS*NF) return;
    int b = idx / NF, f = idx - b*NF;
    const float* gib = gi + (size_t)b*3*NF;
    const float* ghb = gh + (size_t)b*3*NF;
    float r = 1.f / (1.f + expf(-(gib[f]        + ghb[f])));
    float z = 1.f / (1.f + expf(-(gib[NF + f]   + ghb[NF + f])));
    float n = tanhf(gib[2*NF + f] + r * ghb[2*NF + f]);
    hpr[idx] = (1.f - z) * n + z * hpl[idx];
}

// ---------------- RK4 ODE integrator: W rows in registers ----------------
#define ODE_SMEM ((128*129 + 128) * 4)
__global__ __launch_bounds__(128) void ode_kernel(
    const float* __restrict__ hpr, const float* __restrict__ ode_w,
    const float* __restrict__ ode_b, const float* __restrict__ tnode_w,
    const float* __restrict__ tnode_b, const float* __restrict__ hist_ts,
    float* __restrict__ out)
{
    extern __shared__ float sm[];
    float* Wsm = sm;                 // [128][129] transpose-stage, conflict-free
    float* vs  = sm + 128*129;
    int b = blockIdx.x, f = threadIdx.x;
    // coalesced global read, conflict-free smem write
    for (int i = f; i < NF*NF; i += 128) Wsm[(i >> 7)*129 + (i & 127)] = ode_w[i];
    float t0 = hist_ts[b*L + L-2];
    float t1 = hist_ts[b*L + L-1];
    float ratio = t1 - t0;
    float twf = tnode_w[f], tbf = tnode_b[f], obf = ode_b[f];
    float h0 = hpr[(size_t)b*NF + f];
    float z = h0;
    __syncthreads();
    // pull row f of W into registers (bank-conflict-free: stride 129)
    float w[NF];
    #pragma unroll
    for (int k = 0; k < NF; k++) w[k] = Wsm[f*129 + k];
    __syncthreads();

    auto feval = [&](float s, float zin) -> float {
        float t = fmaf(s, ratio, t0);
        vs[f] = zin + cosf(fmaf(t, twf, tbf));
        __syncthreads();
        float acc = obf;
        #pragma unroll
        for (int k = 0; k < NF; k += 4) {
            float4 v = *(const float4*)&vs[k];   // uniform-address broadcast
            acc += v.x * w[k] + v.y * w[k+1] + v.z * w[k+2] + v.w * w[k+3];
        }
        __syncthreads();
        return tanhf(acc) * ratio;
    };

    const float ds = 0.125f;
    for (int st = 0; st < 8; st++) {
        float s = st * ds;
        float k1 = feval(s,            z);
        float k2 = feval(s + 0.5f*ds,  z + 0.5f*ds*k1);
        float k3 = feval(s + 0.5f*ds,  z + 0.5f*ds*k2);
        float k4 = feval(s + ds,       z + ds*k3);
        z += ds * (1.f/6.f) * (k1 + 2.f*k2 + 2.f*k3 + k4);
    }
    out[(size_t)b*NF + f] = z;
    out[(size_t)BS*NF + (size_t)b*NF + f] = h0;
    if (f == 0) out[(size_t)2*BS*NF + b] = t1;
}

// ---------------- launch ----------------
extern "C" void kernel_launch(void* const* d_in, const int* in_sizes, int n_in,
                              void* d_out, int out_size)
{
    const int*   nids      = (const int*)  d_in[0];
    const int*   hist_nids = (const int*)  d_in[2];
    const int*   anon      = (const int*)  d_in[3];
    const int*   eids      = (const int*)  d_in[4];
    const float* hist_ts   = (const float*)d_in[5];
    const int*   dirs      = (const int*)  d_in[6];
    const float* node_feat = (const float*)d_in[7];
    const float* edge_feat = (const float*)d_in[8];
    const float* anony_emb = (const float*)d_in[9];
    const float* time_w    = (const float*)d_in[10];
    const float* time_b    = (const float*)d_in[11];
    const float* in_proj_w = (const float*)d_in[12];
    const float* in_proj_b = (const float*)d_in[13];
    const float* out_proj_w= (const float*)d_in[14];
    const float* out_proj_b= (const float*)d_in[15];
    const float* outfn_w   = (const float*)d_in[16];
    const float* outfn_b   = (const float*)d_in[17];
    const float* attn_wq   = (const float*)d_in[18];
    const float* attn_wk   = (const float*)d_in[19];
    const float* attn_wv   = (const float*)d_in[20];
    const float* merge_w   = (const float*)d_in[21];
    const float* merge_b   = (const float*)d_in[22];
    const float* gru_w_ih  = (const float*)d_in[23];
    const float* gru_w_hh  = (const float*)d_in[24];
    const float* gru_b_ih  = (const float*)d_in[25];
    const float* gru_b_hh  = (const float*)d_in[26];
    const float* ode_w     = (const float*)d_in[27];
    const float* ode_b     = (const float*)d_in[28];
    const float* tnode_w   = (const float*)d_in[29];
    const float* tnode_b   = (const float*)d_in[30];
    float* out = (float*)d_out;

    float *p_full, *p_nb, *p_kv, *p_last, *p_qlast, *p_ctx, *p_mha, *p_qn,
          *p_qh, *p_kh, *p_vh, *p_mrg, *p_hpl, *p_gi, *p_gh, *p_hpr;
    cudaGetSymbolAddress((void**)&p_full,  s_full);
    cudaGetSymbolAddress((void**)&p_nb,    s_nb);
    cudaGetSymbolAddress((void**)&p_kv,    s_kv);
    cudaGetSymbolAddress((void**)&p_last,  s_last);
    cudaGetSymbolAddress((void**)&p_qlast, s_qlast);
    cudaGetSymbolAddress((void**)&p_ctx,   s_ctx);
    cudaGetSymbolAddress((void**)&p_mha,   s_mha);
    cudaGetSymbolAddress((void**)&p_qn,    s_qn);
    cudaGetSymbolAddress((void**)&p_qh,    s_qh);
    cudaGetSymbolAddress((void**)&p_kh,    s_kh);
    cudaGetSymbolAddress((void**)&p_vh,    s_vh);
    cudaGetSymbolAddress((void**)&p_mrg,   s_mrg);
    cudaGetSymbolAddress((void**)&p_hpl,   s_hpl);
    cudaGetSymbolAddress((void**)&p_gi,    s_gi);
    cudaGetSymbolAddress((void**)&p_gh,    s_gh);
    cudaGetSymbolAddress((void**)&p_hpr,   s_hpr);

    build_kernel<<<BS*L, 128>>>(nids, hist_nids, anon, eids, hist_ts, dirs,
                                node_feat, edge_feat, anony_emb, time_w, time_b,
                                p_full, p_nb, p_last);

    // K,V projection: (BS*L,640) @ (1280,640)^T
    gemm_tc<1,0><<<dim3(2*DM/128, BS*L/128), 256>>>(p_full, DM, in_proj_w + (size_t)DM*DM,
                                                    in_proj_b + DM, p_kv, BS*L, 2*DM, DM);
    // Q at last position only (strided A)
    gemm_tc<1,0><<<dim3(DM/128, BS/128), 256>>>(p_full + (size_t)(L-1)*DM, L*DM, in_proj_w,
                                                in_proj_b, p_qlast, BS, DM, DM);
    mha_kernel<<<BS, 256>>>(p_qlast, p_kv, hist_nids, p_ctx);
    gemm_tc<1,0><<<dim3(DM/128, BS/128), 256>>>(p_ctx, DM, out_proj_w, out_proj_b, p_mha, BS, DM, DM);
    gemm_tc<1,0><<<dim3(NF/128, BS/128), 256>>>(p_mha, DM, outfn_w, outfn_b, p_qn, BS, NF, DM);
    gemm_tc<0,0><<<dim3(NF/128, BS/128), 256>>>(p_qn, NF, attn_wq, nullptr, p_qh, BS, NF, NF);
    gemm_tc<0,0><<<dim3(NF/128, BS*L/128), 256>>>(p_nb, NB3, attn_wk, nullptr, p_kh, BS*L, NF, NB3);
    gemm_tc<0,0><<<dim3(NF/128, BS*L/128), 256>>>(p_nb, NB3, attn_wv, nullptr, p_vh, BS*L, NF, NB3);
    attn2_kernel<<<BS, 128>>>(p_qh, p_kh, p_vh, hist_nids, nids, node_feat, p_mrg);
    gemm_tc<0,1><<<dim3(NF/128, BS/128), 256>>>(p_mrg, 2*NF, merge_w, merge_b, p_hpl, BS, NF, 2*NF);
    gemm_tc<1,0><<<dim3(3*NF/128, BS/128), 256>>>(p_last, DIN, gru_w_ih, gru_b_ih, p_gi, BS, 3*NF, DIN);
    gemm_tc<1,0><<<dim3(3*NF/128, BS/128), 256>>>(p_hpl, NF, gru_w_hh, gru_b_hh, p_gh, BS, 3*NF, NF);
    gru_kernel<<<(BS*NF + 255)/256, 256>>>(p_gi, p_gh, p_hpl, p_hpr);
    cudaFuncSetAttribute(ode_kernel, cudaFuncAttributeMaxDynamicSharedMemorySize, ODE_SMEM);
    ode_kernel<<<BS, 128, ODE_SMEM>>>(p_hpr, ode_w, ode_b, tnode_w, tnode_b, hist_ts, out);
}

// round 3
// speedup vs baseline: 2.2534x; 1.1022x over previous
#include <cuda_runtime.h>
#include <math.h>

#define BS   4096
#define L    20
#define NF   128
#define DM   640           // 3*NF + EF + TF
#define DIN  512           // DM - TF
#define DH   320           // DM / NHEAD
#define NB3  384           // NF+EF+TF

// ---------------- scratch (__device__ globals: allocation-free) ----------------
__device__ float s_full[BS*L*DM];
__device__ float s_nb  [BS*L*NB3];
__device__ float s_kv  [BS*L*2*DM];
__device__ float s_last[BS*DIN];
__device__ float s_qlast[BS*DM];
__device__ float s_ctx [BS*DM];
__device__ float s_mha [BS*DM];
__device__ float s_qn  [BS*NF];
__device__ float s_qh  [BS*NF];
__device__ float s_khvh[BS*L*2*NF];      // kh | vh interleaved per row (256)
__device__ float s_wkv [NB3*2*NF];       // packed [attn_wk | attn_wv] as (384,256)
__device__ float s_mrg [BS*2*NF];
__device__ float s_hpl [BS*NF];
__device__ float s_gi  [BS*3*NF];
__device__ float s_gh  [BS*3*NF];
__device__ float s_hpr [BS*NF];

__device__ __forceinline__ unsigned f2tf(float v) {
    unsigned r;
    asm("cvt.rna.tf32.f32 %0, %1;" : "=r"(r) : "f"(v));
    return r;
}

__device__ __forceinline__ void mma_tf32(float c[4], unsigned a0, unsigned a1,
                                         unsigned a2, unsigned a3,
                                         unsigned b0, unsigned b1) {
    asm volatile(
        "mma.sync.aligned.m16n8k8.row.col.f32.tf32.tf32.f32 "
        "{%0,%1,%2,%3}, {%4,%5,%6,%7}, {%8,%9}, {%0,%1,%2,%3};"
        : "+f"(c[0]), "+f"(c[1]), "+f"(c[2]), "+f"(c[3])
        : "r"(a0), "r"(a1), "r"(a2), "r"(a3), "r"(b0), "r"(b1));
}

// ---------------- tf32 tensor-core GEMM, double-buffered ----------------
// C(M,N) = A(M,K; row stride lda) @ B + bias, optional tanh.
// BT=1: B is (N,K) row-major (A@B^T). BT=0: B is (K,N) row-major.
// Block 128x128x16, 256 threads, warp tile 64x32. M%128==0, N%128==0, K%16==0.
template<int BT, int ACT>
__global__ __launch_bounds__(256, 2) void gemm_tc(
    const float* __restrict__ A, int lda,
    const float* __restrict__ B,
    const float* __restrict__ bias,
    float* __restrict__ C,
    int M, int N, int K)
{
    __shared__ __align__(16) unsigned As[2*2048];  // 2 stages, packed frags
    __shared__ __align__(16) unsigned Bs[2*2048];
    const int bm = blockIdx.y * 128;
    const int bn = blockIdx.x * 128;
    const int t  = threadIdx.x;
    const int lane = t & 31;
    const int wr = (t >> 5) >> 2;   // 0..1
    const int wc = (t >> 5) & 3;    // 0..3

    const int ma = t >> 2, ca = t & 3;
    const float* Ag = A + (size_t)(bm + ma) * lda + ca * 4;
    const float* Bg;
    int kb = 0, nb4 = 0, nbr = 0, cb = 0;
    if (BT) { nbr = t >> 2; cb = t & 3; Bg = B + (size_t)(bn + nbr) * K + cb * 4; }
    else    { kb = t >> 5; nb4 = t & 31; Bg = B + (size_t)kb * N + bn + nb4 * 4; }

    float4 ra0, ra1, rb0, rb1;
    auto ldg = [&]() {
        ra0 = *(const float4*)Ag;
        ra1 = *(const float4*)(Ag + (size_t)64 * lda);
        Ag += 16;
        if (BT) {
            rb0 = *(const float4*)Bg;
            rb1 = *(const float4*)(Bg + (size_t)64 * K);
            Bg += 16;
        } else {
            rb0 = *(const float4*)Bg;
            rb1 = *(const float4*)(Bg + (size_t)8 * N);
            Bg += (size_t)16 * N;
        }
    };

    const int imA = ma >> 4, rA = ma & 15, gA = rA & 7, hiA = rA >> 3;
    const int sA = ca >> 1, k2A = ca & 1;
    const int baseA0 = (((sA * 8 + imA)     * 32 + gA * 4) * 4) + k2A * 2 + hiA;
    const int baseA1 = (((sA * 8 + imA + 4) * 32 + gA * 4) * 4) + k2A * 2 + hiA;

    auto sts = [&](int buf) {
        unsigned* Ab = As + buf * 2048;
        unsigned* Bb = Bs + buf * 2048;
        const float* v0 = &ra0.x; const float* v1 = &ra1.x;
        #pragma unroll
        for (int j = 0; j < 4; j++) {
            Ab[baseA0 + 4*j] = f2tf(v0[j]);
            Ab[baseA1 + 4*j] = f2tf(v1[j]);
        }
        if (BT) {
            const int g = nbr & 7, jn0 = (nbr >> 3), jn1 = jn0 + 8;
            const int sB = cb >> 1, regB = cb & 1;
            const int b0 = ((sB * 16 + jn0) * 32 + g * 4) * 2 + regB;
            const int b1 = ((sB * 16 + jn1) * 32 + g * 4) * 2 + regB;
            const float* w0 = &rb0.x; const float* w1 = &rb1.x;
            #pragma unroll
            for (int j = 0; j < 4; j++) {
                Bb[b0 + 2*j] = f2tf(w0[j]);
                Bb[b1 + 2*j] = f2tf(w1[j]);
            }
        } else {
            const int jn = nb4 >> 1, gb = (nb4 & 1) * 4;
            const int tig = kb & 3, regB = (kb >> 2) & 1;
            const int b0 = ((0 * 16 + jn) * 32 + gb * 4 + tig) * 2 + regB;
            const int b1 = ((1 * 16 + jn) * 32 + gb * 4 + tig) * 2 + regB;
            const float* w0 = &rb0.x; const float* w1 = &rb1.x;
            #pragma unroll
            for (int j = 0; j < 4; j++) {
                Bb[b0 + 8*j] = f2tf(w0[j]);
                Bb[b1 + 8*j] = f2tf(w1[j]);
            }
        }
    };

    float acc[4][4][4] = {};

    auto domma = [&](int buf) {
        const unsigned* Ab = As + buf * 2048;
        const unsigned* Bb = Bs + buf * 2048;
        #pragma unroll
        for (int s = 0; s < 2; s++) {
            uint4 af[4]; uint2 bf[4];
            #pragma unroll
            for (int i = 0; i < 4; i++)
                af[i] = *(const uint4*)&Ab[((s*8 + wr*4 + i) * 32 + lane) * 4];
            #pragma unroll
            for (int j = 0; j < 4; j++)
                bf[j] = *(const uint2*)&Bb[((s*16 + wc*4 + j) * 32 + lane) * 2];
            #pragma unroll
            for (int i = 0; i < 4; i++)
                #pragma unroll
                for (int j = 0; j < 4; j++)
                    mma_tf32(acc[i][j], af[i].x, af[i].y, af[i].z, af[i].w,
                             bf[j].x, bf[j].y);
        }
    };

    const int niter = K >> 4;
    ldg();
    sts(0);
    if (niter > 1) ldg();          // prefetch k-iter 1 (in flight during first mma)
    __syncthreads();
    for (int it = 0; it < niter; it++) {
        domma(it & 1);
        if (it + 1 < niter) {
            sts((it + 1) & 1);     // regs from ldg one iter ago
            if (it + 2 < niter) ldg();
        }
        __syncthreads();
    }

    const int g = lane >> 2, tig = lane & 3;
    #pragma unroll
    for (int i = 0; i < 4; i++) {
        int row = bm + wr * 64 + i * 16 + g;
        #pragma unroll
        for (int j = 0; j < 4; j++) {
            int col = bn + wc * 32 + j * 8 + tig * 2;
            float b0 = bias ? bias[col] : 0.f;
            float b1 = bias ? bias[col + 1] : 0.f;
            float v00 = acc[i][j][0] + b0, v01 = acc[i][j][1] + b1;
            float v10 = acc[i][j][2] + b0, v11 = acc[i][j][3] + b1;
            if (ACT == 1) { v00 = tanhf(v00); v01 = tanhf(v01);
                            v10 = tanhf(v10); v11 = tanhf(v11); }
            *(float2*)(C + (size_t)row * N + col)       = make_float2(v00, v01);
            *(float2*)(C + (size_t)(row + 8) * N + col) = make_float2(v10, v11);
        }
    }
}

// ---------------- pack [attn_wk | attn_wv] -> (384, 256) ----------------
__global__ void pack_wkv(const float* __restrict__ wk, const float* __restrict__ wv,
                         float* __restrict__ o)
{
    int k = blockIdx.x, n = threadIdx.x;   // 384 blocks, 256 threads
    o[k * 256 + n] = (n < NF) ? wk[k * NF + n] : wv[k * NF + (n - NF)];
}

// ---------------- gather + feature build ----------------
__global__ __launch_bounds__(128) void build_kernel(
    const int* __restrict__ nids, const int* __restrict__ hist_nids,
    const int* __restrict__ anon_ids, const int* __restrict__ hist_eids,
    const float* __restrict__ hist_ts, const int* __restrict__ hist_dirs,
    const float* __restrict__ node_feat, const float* __restrict__ edge_feat,
    const float* __restrict__ anony_emb, const float* __restrict__ time_w,
    const float* __restrict__ time_b,
    float* __restrict__ full, float* __restrict__ nb, float* __restrict__ last)
{
    int bl = blockIdx.x;
    int b = bl / L, l = bl % L;
    int f = threadIdx.x;
    int nid = nids[b];
    int hn  = hist_nids[bl];
    int dir = hist_dirs[bl];
    int src = dir ? nid : hn;
    int dst = dir ? hn  : nid;
    int eid = hist_eids[bl];
    int aid = anon_ids[bl];
    float dt = hist_ts[b*L + L-1] - hist_ts[bl];
    float sv = node_feat[(size_t)src*NF + f];
    float dv = node_feat[(size_t)dst*NF + f];
    float av = anony_emb[(size_t)aid*NF + f];
    float ev = edge_feat[(size_t)eid*NF + f];
    float tv = cosf(dt * time_w[f] + time_b[f]);
    float hv = node_feat[(size_t)hn*NF + f];
    size_t fb  = (size_t)bl * DM;
    size_t nbb = (size_t)bl * NB3;
    if (l == L-1) {
        size_t lb = (size_t)b * DIN;
        last[lb + f]      = sv;
        last[lb + NF + f] = dv;
        last[lb + 2*NF+f] = av;
        last[lb + 3*NF+f] = ev;
        full[fb + f] = 0.f; full[fb + NF + f] = 0.f;
        full[fb + 2*NF + f] = 0.f; full[fb + 3*NF + f] = 0.f;
    } else {
        full[fb + f] = sv; full[fb + NF + f] = dv;
        full[fb + 2*NF + f] = av; full[fb + 3*NF + f] = ev;
    }
    full[fb + 4*NF + f] = tv;
    nb[nbb + f] = hv; nb[nbb + NF + f] = ev; nb[nbb + 2*NF + f] = tv;
}

// ---------------- MHA at last query position only ----------------
__global__ __launch_bounds__(256) void mha_kernel(
    const float* __restrict__ qlast, const float* __restrict__ kv,
    const int* __restrict__ hist_nids, float* __restrict__ ctx)
{
    int b = blockIdx.x;
    __shared__ float qs[DM];
    __shared__ float sc[2*L];
    int t = threadIdx.x;
    for (int d = t; d < DM; d += 256) qs[d] = qlast[(size_t)b*DM + d];
    __syncthreads();
    int w = t >> 5, lane = t & 31;
    for (int p = w; p < 2*L; p += 8) {
        int h = p / L, m = p % L;
        const float* kp = kv + (size_t)(b*L + m)*(2*DM) + h*DH;
        const float* qp = qs + h*DH;
        float s = 0.f;
        for (int d = lane; d < DH; d += 32) s += qp[d] * kp[d];
        #pragma unroll
        for (int o = 16; o; o >>= 1) s += __shfl_xor_sync(0xffffffffu, s, o);
        if (lane == 0) {
            bool msk = (hist_nids[b*L + m] == 0) && (m != L-1);
            sc[p] = msk ? -1e9f : s * (1.f / sqrtf((float)DH));
        }
    }
    __syncthreads();
    if (t < 2) {
        float mx = -1e30f;
        for (int m = 0; m < L; m++) mx = fmaxf(mx, sc[t*L + m]);
        float sum = 0.f;
        for (int m = 0; m < L; m++) { float e = expf(sc[t*L + m] - mx); sc[t*L + m] = e; sum += e; }
        float inv = 1.f / sum;
        for (int m = 0; m < L; m++) sc[t*L + m] *= inv;
    }
    __syncthreads();
    for (int d = t; d < DM; d += 256) {
        int h = d / DH, dd = d - h*DH;
        const float* vp = kv + (size_t)(b*L)*(2*DM) + DM + h*DH + dd;
        float acc = 0.f;
        #pragma unroll
        for (int m = 0; m < L; m++) acc += sc[h*L + m] * vp[(size_t)m*(2*DM)];
        ctx[(size_t)b*DM + d] = acc;
    }
}

// ---------------- pooling attention + merge-input build ----------------
__global__ __launch_bounds__(128) void attn2_kernel(
    const float* __restrict__ qh, const float* __restrict__ khvh,
    const int* __restrict__ hist_nids,
    const int* __restrict__ nids, const float* __restrict__ node_feat,
    float* __restrict__ mergein)
{
    int b = blockIdx.x, t = threadIdx.x;
    __shared__ float q[NF];
    __shared__ float a[L];
    q[t] = qh[(size_t)b*NF + t];
    __syncthreads();
    int w = t >> 5, lane = t & 31;
    for (int l = w; l < L; l += 4) {
        const float* kp = khvh + (size_t)(b*L + l)*(2*NF);
        float s = 0.f;
        #pragma unroll
        for (int d = lane; d < NF; d += 32) s += q[d] * kp[d];
        #pragma unroll
        for (int o = 16; o; o >>= 1) s += __shfl_xor_sync(0xffffffffu, s, o);
        if (lane == 0) {
            bool msk = (hist_nids[b*L + l] == 0) && (l != L-1);
            a[l] = msk ? -1e9f : s * (1.f / sqrtf((float)NF));
        }
    }
    __syncthreads();
    if (t == 0) {
        float mx = -1e30f;
        for (int l = 0; l < L; l++) mx = fmaxf(mx, a[l]);
        float sum = 0.f;
        for (int l = 0; l < L; l++) { float e = expf(a[l] - mx); a[l] = e; sum += e; }
        float inv = 1.f / sum;
        for (int l = 0; l < L; l++) a[l] *= inv;
    }
    __syncthreads();
    float acc = 0.f;
    #pragma unroll
    for (int l = 0; l < L; l++) acc += a[l] * khvh[(size_t)(b*L + l)*(2*NF) + NF + t];
    mergein[(size_t)b*2*NF + t]      = acc;
    mergein[(size_t)b*2*NF + NF + t] = node_feat[(size_t)nids[b]*NF + t];
}

// ---------------- GRU cell elementwise ----------------
__global__ void gru_kernel(const float* __restrict__ gi, const float* __restrict__ gh,
                           const float* __restrict__ hpl, float* __restrict__ hpr)
{
    int idx = blockIdx.x * blockDim.x + threadIdx.x;
    if (idx >= BS*NF) return;
    int b = idx / NF, f = idx - b*NF;
    const float* gib = gi + (size_t)b*3*NF;
    const float* ghb = gh + (size_t)b*3*NF;
    float r = 1.f / (1.f + expf(-(gib[f]        + ghb[f])));
    float z = 1.f / (1.f + expf(-(gib[NF + f]   + ghb[NF + f])));
    float n = tanhf(gib[2*NF + f] + r * ghb[2*NF + f]);
    hpr[idx] = (1.f - z) * n + z * hpl[idx];
}

// ---------------- RK4 ODE integrator: W rows in registers ----------------
#define ODE_SMEM ((128*129 + 128) * 4)
__global__ __launch_bounds__(128) void ode_kernel(
    const float* __restrict__ hpr, const float* __restrict__ ode_w,
    const float* __restrict__ ode_b, const float* __restrict__ tnode_w,
    const float* __restrict__ tnode_b, const float* __restrict__ hist_ts,
    float* __restrict__ out)
{
    extern __shared__ float sm[];
    float* Wsm = sm;
    float* vs  = sm + 128*129;
    int b = blockIdx.x, f = threadIdx.x;
    for (int i = f; i < NF*NF; i += 128) Wsm[(i >> 7)*129 + (i & 127)] = ode_w[i];
    float t0 = hist_ts[b*L + L-2];
    float t1 = hist_ts[b*L + L-1];
    float ratio = t1 - t0;
    float twf = tnode_w[f], tbf = tnode_b[f], obf = ode_b[f];
    float h0 = hpr[(size_t)b*NF + f];
    float z = h0;
    __syncthreads();
    float w[NF];
    #pragma unroll
    for (int k = 0; k < NF; k++) w[k] = Wsm[f*129 + k];
    __syncthreads();

    auto feval = [&](float s, float zin) -> float {
        float t = fmaf(s, ratio, t0);
        vs[f] = zin + cosf(fmaf(t, twf, tbf));
        __syncthreads();
        float acc = obf;
        #pragma unroll
        for (int k = 0; k < NF; k += 4) {
            float4 v = *(const float4*)&vs[k];
            acc += v.x * w[k] + v.y * w[k+1] + v.z * w[k+2] + v.w * w[k+3];
        }
        __syncthreads();
        return tanhf(acc) * ratio;
    };

    const float ds = 0.125f;
    for (int st = 0; st < 8; st++) {
        float s = st * ds;
        float k1 = feval(s,            z);
        float k2 = feval(s + 0.5f*ds,  z + 0.5f*ds*k1);
        float k3 = feval(s + 0.5f*ds,  z + 0.5f*ds*k2);
        float k4 = feval(s + ds,       z + ds*k3);
        z += ds * (1.f/6.f) * (k1 + 2.f*k2 + 2.f*k3 + k4);
    }
    out[(size_t)b*NF + f] = z;
    out[(size_t)BS*NF + (size_t)b*NF + f] = h0;
    if (f == 0) out[(size_t)2*BS*NF + b] = t1;
}

// ---------------- launch ----------------
extern "C" void kernel_launch(void* const* d_in, const int* in_sizes, int n_in,
                              void* d_out, int out_size)
{
    const int*   nids      = (const int*)  d_in[0];
    const int*   hist_nids = (const int*)  d_in[2];
    const int*   anon      = (const int*)  d_in[3];
    const int*   eids      = (const int*)  d_in[4];
    const float* hist_ts   = (const float*)d_in[5];
    const int*   dirs      = (const int*)  d_in[6];
    const float* node_feat = (const float*)d_in[7];
    const float* edge_feat = (const float*)d_in[8];
    const float* anony_emb = (const float*)d_in[9];
    const float* time_w    = (const float*)d_in[10];
    const float* time_b    = (const float*)d_in[11];
    const float* in_proj_w = (const float*)d_in[12];
    const float* in_proj_b = (const float*)d_in[13];
    const float* out_proj_w= (const float*)d_in[14];
    const float* out_proj_b= (const float*)d_in[15];
    const float* outfn_w   = (const float*)d_in[16];
    const float* outfn_b   = (const float*)d_in[17];
    const float* attn_wq   = (const float*)d_in[18];
    const float* attn_wk   = (const float*)d_in[19];
    const float* attn_wv   = (const float*)d_in[20];
    const float* merge_w   = (const float*)d_in[21];
    const float* merge_b   = (const float*)d_in[22];
    const float* gru_w_ih  = (const float*)d_in[23];
    const float* gru_w_hh  = (const float*)d_in[24];
    const float* gru_b_ih  = (const float*)d_in[25];
    const float* gru_b_hh  = (const float*)d_in[26];
    const float* ode_w     = (const float*)d_in[27];
    const float* ode_b     = (const float*)d_in[28];
    const float* tnode_w   = (const float*)d_in[29];
    const float* tnode_b   = (const float*)d_in[30];
    float* out = (float*)d_out;

    float *p_full, *p_nb, *p_kv, *p_last, *p_qlast, *p_ctx, *p_mha, *p_qn,
          *p_qh, *p_khvh, *p_wkv, *p_mrg, *p_hpl, *p_gi, *p_gh, *p_hpr;
    cudaGetSymbolAddress((void**)&p_full,  s_full);
    cudaGetSymbolAddress((void**)&p_nb,    s_nb);
    cudaGetSymbolAddress((void**)&p_kv,    s_kv);
    cudaGetSymbolAddress((void**)&p_last,  s_last);
    cudaGetSymbolAddress((void**)&p_qlast, s_qlast);
    cudaGetSymbolAddress((void**)&p_ctx,   s_ctx);
    cudaGetSymbolAddress((void**)&p_mha,   s_mha);
    cudaGetSymbolAddress((void**)&p_qn,    s_qn);
    cudaGetSymbolAddress((void**)&p_qh,    s_qh);
    cudaGetSymbolAddress((void**)&p_khvh,  s_khvh);
    cudaGetSymbolAddress((void**)&p_wkv,   s_wkv);
    cudaGetSymbolAddress((void**)&p_mrg,   s_mrg);
    cudaGetSymbolAddress((void**)&p_hpl,   s_hpl);
    cudaGetSymbolAddress((void**)&p_gi,    s_gi);
    cudaGetSymbolAddress((void**)&p_gh,    s_gh);
    cudaGetSymbolAddress((void**)&p_hpr,   s_hpr);

    build_kernel<<<BS*L, 128>>>(nids, hist_nids, anon, eids, hist_ts, dirs,
                                node_feat, edge_feat, anony_emb, time_w, time_b,
                                p_full, p_nb, p_last);
    pack_wkv<<<NB3, 256>>>(attn_wk, attn_wv, p_wkv);

    // K,V projection: (BS*L,640) @ (1280,640)^T
    gemm_tc<1,0><<<dim3(2*DM/128, BS*L/128), 256>>>(p_full, DM, in_proj_w + (size_t)DM*DM,
                                                    in_proj_b + DM, p_kv, BS*L, 2*DM, DM);
    // Q at last position only
    gemm_tc<1,0><<<dim3(DM/128, BS/128), 256>>>(p_full + (size_t)(L-1)*DM, L*DM, in_proj_w,
                                                in_proj_b, p_qlast, BS, DM, DM);
    mha_kernel<<<BS, 256>>>(p_qlast, p_kv, hist_nids, p_ctx);
    gemm_tc<1,0><<<dim3(DM/128, BS/128), 256>>>(p_ctx, DM, out_proj_w, out_proj_b, p_mha, BS, DM, DM);
    gemm_tc<1,0><<<dim3(NF/128, BS/128), 256>>>(p_mha, DM, outfn_w, outfn_b, p_qn, BS, NF, DM);
    gemm_tc<0,0><<<dim3(NF/128, BS/128), 256>>>(p_qn, NF, attn_wq, nullptr, p_qh, BS, NF, NF);
    // merged kh|vh: (BS*L,384) @ (384,256)
    gemm_tc<0,0><<<dim3(2*NF/128, BS*L/128), 256>>>(p_nb, NB3, p_wkv, nullptr, p_khvh, BS*L, 2*NF, NB3);
    attn2_kernel<<<BS, 128>>>(p_qh, p_khvh, hist_nids, nids, node_feat, p_mrg);
    gemm_tc<0,1><<<dim3(NF/128, BS/128), 256>>>(p_mrg, 2*NF, merge_w, merge_b, p_hpl, BS, NF, 2*NF);
    gemm_tc<1,0><<<dim3(3*NF/128, BS/128), 256>>>(p_last, DIN, gru_w_ih, gru_b_ih, p_gi, BS, 3*NF, DIN);
    gemm_tc<1,0><<<dim3(3*NF/128, BS/128), 256>>>(p_hpl, NF, gru_w_hh, gru_b_hh, p_gh, BS, 3*NF, NF);
    gru_kernel<<<(BS*NF + 255)/256, 256>>>(p_gi, p_gh, p_hpl, p_hpr);
    cudaFuncSetAttribute(ode_kernel, cudaFuncAttributeMaxDynamicSharedMemorySize, ODE_SMEM);
    ode_kernel<<<BS, 128, ODE_SMEM>>>(p_hpr, ode_w, ode_b, tnode_w, tnode_b, hist_ts, out);
}

// round 5
// speedup vs baseline: 5.3221x; 2.3618x over previous
#include <cuda_runtime.h>
#include <math.h>
#include <stdint.h>

#define BS   4096
#define L    20
#define NF   128
#define DM   640
#define DIN  512
#define DH   320
#define NB3  384

// ---------------- scratch (__device__ globals) ----------------
__device__ float g_last [BS*DIN];      // last_event_feat
__device__ float g_wctx [BS*2*DM];     // per-head weighted feature sums
__device__ float g_ctx  [BS*DM];
__device__ float g_qh   [BS*NF];
__device__ float g_qh2  [BS*NB3];
__device__ float g_wnb  [BS*NB3];
__device__ float g_mrg  [BS*2*NF];
__device__ float g_hpl  [BS*NF];
__device__ float g_gi   [BS*3*NF];
__device__ float g_gh   [BS*3*NF];
__device__ float g_hpr  [BS*NF];
__device__ float g_q0   [DM];          // constant query vector
__device__ float g_q2   [2*DM];        // per-head folded query
__device__ float g_Wqt  [NF*NF];
__device__ float g_T2   [NF*DM];
__device__ float g_Gt   [NF*DM];       // fused (out_proj∘outfn∘attn_wq)^T
__device__ float g_bqh  [NF];
__device__ float g_W2   [DM*2*DM];     // block-diag Wv (640 x 1280)

__device__ __forceinline__ unsigned f2tf(float v) {
    unsigned r;
    asm("cvt.rna.tf32.f32 %0, %1;" : "=r"(r) : "f"(v));
    return r;
}

__device__ __forceinline__ void mma_tf32(float c[4], unsigned a0, unsigned a1,
                                         unsigned a2, unsigned a3,
                                         unsigned b0, unsigned b1) {
    asm volatile(
        "mma.sync.aligned.m16n8k8.row.col.f32.tf32.tf32.f32 "
        "{%0,%1,%2,%3}, {%4,%5,%6,%7}, {%8,%9}, {%0,%1,%2,%3};"
        : "+f"(c[0]), "+f"(c[1]), "+f"(c[2]), "+f"(c[3])
        : "r"(a0), "r"(a1), "r"(a2), "r"(a3), "r"(b0), "r"(b1));
}

// ---------------- tf32 mma.sync GEMM, double-buffered ----------------
// BT=1: C = A @ B^T + bias (B is (N,K) rows at ldb).  BT=0: C = A @ B (B is (K,N) at ldb).
// Block 128x128x16, 256 threads. M%128==0, N%128==0, K%16==0.
template<int BT, int ACT>
__global__ __launch_bounds__(256, 2) void gemm_tc(
    const float* __restrict__ A, int lda,
    const float* __restrict__ B, int ldb,
    const float* __restrict__ bias,
    float* __restrict__ C, int ldc,
    int M, int N, int K)
{
    __shared__ __align__(16) unsigned As[2*2048];
    __shared__ __align__(16) unsigned Bs[2*2048];
    const int bm = blockIdx.y * 128;
    const int bn = blockIdx.x * 128;
    const int t  = threadIdx.x;
    const int lane = t & 31;
    const int wr = (t >> 5) >> 2;
    const int wc = (t >> 5) & 3;

    const int ma = t >> 2, ca = t & 3;
    const float* Ag = A + (size_t)(bm + ma) * lda + ca * 4;
    const float* Bg;
    int kb = 0, nb4 = 0, nbr = 0, cb = 0;
    if (BT) { nbr = t >> 2; cb = t & 3; Bg = B + (size_t)(bn + nbr) * ldb + cb * 4; }
    else    { kb = t >> 5; nb4 = t & 31; Bg = B + (size_t)kb * ldb + bn + nb4 * 4; }

    float4 ra0, ra1, rb0, rb1;
    auto ldg = [&]() {
        ra0 = *(const float4*)Ag;
        ra1 = *(const float4*)(Ag + (size_t)64 * lda);
        Ag += 16;
        if (BT) {
            rb0 = *(const float4*)Bg;
            rb1 = *(const float4*)(Bg + (size_t)64 * ldb);
            Bg += 16;
        } else {
            rb0 = *(const float4*)Bg;
            rb1 = *(const float4*)(Bg + (size_t)8 * ldb);
            Bg += (size_t)16 * ldb;
        }
    };

    const int imA = ma >> 4, rA = ma & 15, gA = rA & 7, hiA = rA >> 3;
    const int sA = ca >> 1, k2A = ca & 1;
    const int baseA0 = (((sA * 8 + imA)     * 32 + gA * 4) * 4) + k2A * 2 + hiA;
    const int baseA1 = (((sA * 8 + imA + 4) * 32 + gA * 4) * 4) + k2A * 2 + hiA;

    auto sts = [&](int buf) {
        unsigned* Ab = As + buf * 2048;
        unsigned* Bb = Bs + buf * 2048;
        const float* v0 = &ra0.x; const float* v1 = &ra1.x;
        #pragma unroll
        for (int j = 0; j < 4; j++) {
            Ab[baseA0 + 4*j] = f2tf(v0[j]);
            Ab[baseA1 + 4*j] = f2tf(v1[j]);
        }
        if (BT) {
            const int g = nbr & 7, jn0 = (nbr >> 3), jn1 = jn0 + 8;
            const int sB = cb >> 1, regB = cb & 1;
            const int b0 = ((sB * 16 + jn0) * 32 + g * 4) * 2 + regB;
            const int b1 = ((sB * 16 + jn1) * 32 + g * 4) * 2 + regB;
            const float* w0 = &rb0.x; const float* w1 = &rb1.x;
            #pragma unroll
            for (int j = 0; j < 4; j++) {
                Bb[b0 + 2*j] = f2tf(w0[j]);
                Bb[b1 + 2*j] = f2tf(w1[j]);
            }
        } else {
            const int jn = nb4 >> 1, gb = (nb4 & 1) * 4;
            const int tig = kb & 3, regB = (kb >> 2) & 1;
            const int b0 = ((0 * 16 + jn) * 32 + gb * 4 + tig) * 2 + regB;
            const int b1 = ((1 * 16 + jn) * 32 + gb * 4 + tig) * 2 + regB;
            const float* w0 = &rb0.x; const float* w1 = &rb1.x;
            #pragma unroll
            for (int j = 0; j < 4; j++) {
                Bb[b0 + 8*j] = f2tf(w0[j]);
                Bb[b1 + 8*j] = f2tf(w1[j]);
            }
        }
    };

    float acc[4][4][4] = {};
    auto domma = [&](int buf) {
        const unsigned* Ab = As + buf * 2048;
        const unsigned* Bb = Bs + buf * 2048;
        #pragma unroll
        for (int s = 0; s < 2; s++) {
            uint4 af[4]; uint2 bf[4];
            #pragma unroll
            for (int i = 0; i < 4; i++)
                af[i] = *(const uint4*)&Ab[((s*8 + wr*4 + i) * 32 + lane) * 4];
            #pragma unroll
            for (int j = 0; j < 4; j++)
                bf[j] = *(const uint2*)&Bb[((s*16 + wc*4 + j) * 32 + lane) * 2];
            #pragma unroll
            for (int i = 0; i < 4; i++)
                #pragma unroll
                for (int j = 0; j < 4; j++)
                    mma_tf32(acc[i][j], af[i].x, af[i].y, af[i].z, af[i].w,
                             bf[j].x, bf[j].y);
        }
    };

    const int niter = K >> 4;
    ldg();
    sts(0);
    if (niter > 1) ldg();
    __syncthreads();
    for (int it = 0; it < niter; it++) {
        domma(it & 1);
        if (it + 1 < niter) {
            sts((it + 1) & 1);
            if (it + 2 < niter) ldg();
        }
        __syncthreads();
    }

    const int g = lane >> 2, tig = lane & 3;
    #pragma unroll
    for (int i = 0; i < 4; i++) {
        int row = bm + wr * 64 + i * 16 + g;
        #pragma unroll
        for (int j = 0; j < 4; j++) {
            int col = bn + wc * 32 + j * 8 + tig * 2;
            float b0 = bias ? bias[col] : 0.f;
            float b1 = bias ? bias[col + 1] : 0.f;
            float v00 = acc[i][j][0] + b0, v01 = acc[i][j][1] + b1;
            float v10 = acc[i][j][2] + b0, v11 = acc[i][j][3] + b1;
            if (ACT == 1) { v00 = tanhf(v00); v01 = tanhf(v01);
                            v10 = tanhf(v10); v11 = tanhf(v11); }
            *(float2*)(C + (size_t)row * ldc + col)       = make_float2(v00, v01);
            *(float2*)(C + (size_t)(row + 8) * ldc + col) = make_float2(v10, v11);
        }
    }
}

// ---------------- prep kernels ----------------
// q0 = [0,0,0,0,cos(time_b)] @ in_proj_w[0:640]^T + in_proj_b[0:640]
__global__ void qprep1(const float* __restrict__ ipw, const float* __restrict__ ipb,
                       const float* __restrict__ time_b, float* __restrict__ q0)
{
    __shared__ float tsl[NF];
    int t = threadIdx.x;             // 640 threads
    if (t < NF) tsl[t] = cosf(time_b[t]);
    __syncthreads();
    float acc = ipb[t];
    const float* row = ipw + (size_t)t * DM + DIN;
    for (int k = 0; k < NF; k++) acc += tsl[k] * row[k];
    q0[t] = acc;
}
// q2[h][j] = sum_d q0[h*320+d] * Wk[h*320+d][j],  Wk = in_proj_w rows 640..1280
__global__ void qprep2(const float* __restrict__ ipw, const float* __restrict__ q0,
                       float* __restrict__ q2)
{
    __shared__ float qs[DH];
    int h = blockIdx.x, j = threadIdx.x;   // 2 blocks, 640 threads
    for (int i = j; i < DH; i += DM) qs[i] = q0[h*DH + i];
    __syncthreads();
    float acc = 0.f;
    const float* base = ipw + (size_t)(DM + h*DH) * DM + j;
    for (int d = 0; d < DH; d++) acc += qs[d] * base[(size_t)d * DM];
    q2[h*DM + j] = acc;
}
__global__ void transWq(const float* __restrict__ wq, float* __restrict__ o) {
    o[blockIdx.x * NF + threadIdx.x] = wq[threadIdx.x * NF + blockIdx.x];
}
// biasqh = (outfn_w@out_proj_b + outfn_b) @ attn_wq
__global__ void biasqh_k(const float* __restrict__ wf, const float* __restrict__ bo,
                         const float* __restrict__ bf, const float* __restrict__ wq,
                         float* __restrict__ o)
{
    __shared__ float b1[NF];
    int t = threadIdx.x;             // 128
    float acc = bf[t];
    const float* row = wf + (size_t)t * DM;
    for (int k = 0; k < DM; k++) acc += row[k] * bo[k];
    b1[t] = acc;
    __syncthreads();
    float s = 0.f;
    for (int i = 0; i < NF; i++) s += b1[i] * wq[i * NF + t];
    o[t] = s;
}
// W2 (640 x 1280): block-diag [Wv_h0 | 0 ; 0 | Wv_h1], Wv = in_proj_w rows 1280..1920
__global__ void packW2(const float* __restrict__ ipw, float* __restrict__ o) {
    int d = blockIdx.x;              // 640
    int h = d / DH;
    for (int c = threadIdx.x; c < 2*DM; c += 256) {
        float v = (c / DM == h) ? ipw[(size_t)(2*DM + d) * DM + (c % DM)] : 0.f;
        o[(size_t)d * (2*DM) + c] = v;
    }
}

// ---------------- MHA stage: gather + scores(const q2) + weighted sums ----------------
#define MHA2_SMEM ((L*DM + 2*DM + 64) * 4 + L*5*4)
__global__ __launch_bounds__(256) void mha2_kernel(
    const int* __restrict__ nids, const int* __restrict__ hist_nids,
    const int* __restrict__ anon_ids, const int* __restrict__ hist_eids,
    const float* __restrict__ hist_ts, const int* __restrict__ hist_dirs,
    const float* __restrict__ node_feat, const float* __restrict__ edge_feat,
    const float* __restrict__ anony_emb, const float* __restrict__ time_w,
    const float* __restrict__ time_b, const float* __restrict__ q2,
    float* __restrict__ wctx, float* __restrict__ last)
{
    extern __shared__ float sm[];
    float* rows = sm;                 // [L][640]
    float* q2s  = sm + L*DM;          // [1280]
    float* sc   = q2s + 2*DM;         // [40] (+pad to 64)
    int*   hn   = (int*)(sc + 64);
    int*   eid  = hn + L;
    int*   aid  = eid + L;
    int*   dirr = aid + L;
    float* dts  = (float*)(dirr + L);

    int b = blockIdx.x, t = threadIdx.x;
    if (t < L) {
        hn[t]  = hist_nids[b*L + t];
        eid[t] = hist_eids[b*L + t];
        aid[t] = anon_ids[b*L + t];
        dirr[t] = hist_dirs[b*L + t];
        dts[t] = hist_ts[b*L + L-1] - hist_ts[b*L + t];
    }
    for (int i = t; i < 2*DM; i += 256) q2s[i] = q2[i];
    __syncthreads();
    int nid = nids[b];

    for (int idx = t; idx < L*DM; idx += 256) {
        int m = idx / DM, d = idx - m*DM;
        float v;
        if (d < NF) {
            int src = dirr[m] ? nid : hn[m];
            v = node_feat[(size_t)src*NF + d];
        } else if (d < 2*NF) {
            int dst = dirr[m] ? hn[m] : nid;
            v = node_feat[(size_t)dst*NF + (d - NF)];
        } else if (d < 3*NF) {
            v = anony_emb[(size_t)aid[m]*NF + (d - 2*NF)];
        } else if (d < 4*NF) {
            v = edge_feat[(size_t)eid[m]*NF + (d - 3*NF)];
        } else {
            int f = d - 4*NF;
            v = cosf(fmaf(dts[m], time_w[f], time_b[f]));
        }
        if (m == L-1 && d < DIN) {
            last[(size_t)b*DIN + d] = v;
            v = 0.f;
        }
        rows[idx] = v;
    }
    __syncthreads();

    int w = t >> 5, lane = t & 31;
    for (int p = w; p < 2*L; p += 8) {
        int h = p / L, m = p - h*L;
        const float* qp = q2s + h*DM;
        const float* rp = rows + m*DM;
        float s = 0.f;
        for (int d = lane; d < DM; d += 32) s += qp[d] * rp[d];
        #pragma unroll
        for (int o = 16; o; o >>= 1) s += __shfl_xor_sync(0xffffffffu, s, o);
        if (lane == 0) {
            bool msk = (hn[m] == 0) && (m != L-1);
            sc[h*L + m] = msk ? -1e9f : s * (1.f / sqrtf((float)DH));
        }
    }
    __syncthreads();
    if (t < 2) {
        float mx = -1e30f;
        for (int m = 0; m < L; m++) mx = fmaxf(mx, sc[t*L + m]);
        float sum = 0.f;
        for (int m = 0; m < L; m++) { float e = expf(sc[t*L + m] - mx); sc[t*L + m] = e; sum += e; }
        float inv = 1.f / sum;
        for (int m = 0; m < L; m++) sc[t*L + m] *= inv;
    }
    __syncthreads();
    for (int i = t; i < 2*DM; i += 256) {
        int h = i / DM, d = i - h*DM;
        float acc = 0.f;
        #pragma unroll
        for (int m = 0; m < L; m++) acc += sc[h*L + m] * rows[m*DM + d];
        wctx[(size_t)b*(2*DM) + i] = acc;
    }
}

// ---------------- pooling attention stage ----------------
#define ATT2_SMEM ((L*NB3 + NB3 + 32) * 4 + L*3*4)
__global__ __launch_bounds__(128) void attn2_kernel(
    const int* __restrict__ nids, const int* __restrict__ hist_nids,
    const int* __restrict__ hist_eids, const float* __restrict__ hist_ts,
    const float* __restrict__ node_feat, const float* __restrict__ edge_feat,
    const float* __restrict__ time_w, const float* __restrict__ time_b,
    const float* __restrict__ qh2,
    float* __restrict__ wnb, float* __restrict__ mergein)
{
    extern __shared__ float sm[];
    float* rows = sm;                 // [L][384]
    float* qs   = sm + L*NB3;         // [384]
    float* a    = qs + NB3;           // [20] (+pad 32)
    int*   hn   = (int*)(a + 32);
    int*   eid  = hn + L;
    float* dts  = (float*)(eid + L);

    int b = blockIdx.x, t = threadIdx.x;
    if (t < L) {
        hn[t]  = hist_nids[b*L + t];
        eid[t] = hist_eids[b*L + t];
        dts[t] = hist_ts[b*L + L-1] - hist_ts[b*L + t];
    }
    for (int i = t; i < NB3; i += 128) qs[i] = qh2[(size_t)b*NB3 + i];
    __syncthreads();

    for (int idx = t; idx < L*NB3; idx += 128) {
        int m = idx / NB3, d = idx - m*NB3;
        float v;
        if (d < NF)          v = node_feat[(size_t)hn[m]*NF + d];
        else if (d < 2*NF)   v = edge_feat[(size_t)eid[m]*NF + (d - NF)];
        else {
            int f = d - 2*NF;
            v = cosf(fmaf(dts[m], time_w[f], time_b[f]));
        }
        rows[idx] = v;
    }
    __syncthreads();

    int w = t >> 5, lane = t & 31;
    for (int l = w; l < L; l += 4) {
        const float* rp = rows + l*NB3;
        float s = 0.f;
        for (int d = lane; d < NB3; d += 32) s += qs[d] * rp[d];
        #pragma unroll
        for (int o = 16; o; o >>= 1) s += __shfl_xor_sync(0xffffffffu, s, o);
        if (lane == 0) {
            bool msk = (hn[l] == 0) && (l != L-1);
            a[l] = msk ? -1e9f : s * (1.f / sqrtf((float)NF));
        }
    }
    __syncthreads();
    if (t == 0) {
        float mx = -1e30f;
        for (int l = 0; l < L; l++) mx = fmaxf(mx, a[l]);
        float sum = 0.f;
        for (int l = 0; l < L; l++) { float e = expf(a[l] - mx); a[l] = e; sum += e; }
        float inv = 1.f / sum;
        for (int l = 0; l < L; l++) a[l] *= inv;
    }
    __syncthreads();
    for (int d = t; d < NB3; d += 128) {
        float acc = 0.f;
        #pragma unroll
        for (int l = 0; l < L; l++) acc += a[l] * rows[l*NB3 + d];
        wnb[(size_t)b*NB3 + d] = acc;
    }
    if (t < NF)
        mergein[(size_t)b*2*NF + NF + t] = node_feat[(size_t)nids[b]*NF + t];
}

// ---------------- GRU ----------------
__global__ void gru_kernel(const float* __restrict__ gi, const float* __restrict__ gh,
                           const float* __restrict__ hpl, float* __restrict__ hpr)
{
    int idx = blockIdx.x * blockDim.x + threadIdx.x;
    if (idx >= BS*NF) return;
    int b = idx / NF, f = idx - b*NF;
    const float* gib = gi + (size_t)b*3*NF;
    const float* ghb = gh + (size_t)b*3*NF;
    float r = 1.f / (1.f + expf(-(gib[f]      + ghb[f])));
    float z = 1.f / (1.f + expf(-(gib[NF + f] + ghb[NF + f])));
    float n = tanhf(gib[2*NF + f] + r * ghb[2*NF + f]);
    hpr[idx] = (1.f - z) * n + z * hpl[idx];
}

// ---------------- RK4 ODE ----------------
#define ODE_SMEM ((128*129 + 128) * 4)
__global__ __launch_bounds__(128) void ode_kernel(
    const float* __restrict__ hpr, const float* __restrict__ ode_w,
    const float* __restrict__ ode_b, const float* __restrict__ tnode_w,
    const float* __restrict__ tnode_b, const float* __restrict__ hist_ts,
    float* __restrict__ out)
{
    extern __shared__ float sm[];
    float* Wsm = sm;
    float* vs  = sm + 128*129;
    int b = blockIdx.x, f = threadIdx.x;
    for (int i = f; i < NF*NF; i += 128) Wsm[(i >> 7)*129 + (i & 127)] = ode_w[i];
    float t0 = hist_ts[b*L + L-2];
    float t1 = hist_ts[b*L + L-1];
    float ratio = t1 - t0;
    float twf = tnode_w[f], tbf = tnode_b[f], obf = ode_b[f];
    float h0 = hpr[(size_t)b*NF + f];
    float z = h0;
    __syncthreads();
    float w[NF];
    #pragma unroll
    for (int k = 0; k < NF; k++) w[k] = Wsm[f*129 + k];
    __syncthreads();

    auto feval = [&](float s, float zin) -> float {
        float t = fmaf(s, ratio, t0);
        vs[f] = zin + cosf(fmaf(t, twf, tbf));
        __syncthreads();
        float acc = obf;
        #pragma unroll
        for (int k = 0; k < NF; k += 4) {
            float4 v = *(const float4*)&vs[k];
            acc += v.x * w[k] + v.y * w[k+1] + v.z * w[k+2] + v.w * w[k+3];
        }
        __syncthreads();
        return tanhf(acc) * ratio;
    };

    const float ds = 0.125f;
    for (int st = 0; st < 8; st++) {
        float s = st * ds;
        float k1 = feval(s,            z);
        float k2 = feval(s + 0.5f*ds,  z + 0.5f*ds*k1);
        float k3 = feval(s + 0.5f*ds,  z + 0.5f*ds*k2);
        float k4 = feval(s + ds,       z + ds*k3);
        z += ds * (1.f/6.f) * (k1 + 2.f*k2 + 2.f*k3 + k4);
    }
    out[(size_t)b*NF + f] = z;
    out[(size_t)BS*NF + (size_t)b*NF + f] = h0;
    if (f == 0) out[(size_t)2*BS*NF + b] = t1;
}

// ---------------- launch ----------------
extern "C" void kernel_launch(void* const* d_in, const int* in_sizes, int n_in,
                              void* d_out, int out_size)
{
    const int*   nids      = (const int*)  d_in[0];
    const int*   hist_nids = (const int*)  d_in[2];
    const int*   anon      = (const int*)  d_in[3];
    const int*   eids      = (const int*)  d_in[4];
    const float* hist_ts   = (const float*)d_in[5];
    const int*   dirs      = (const int*)  d_in[6];
    const float* node_feat = (const float*)d_in[7];
    const float* edge_feat = (const float*)d_in[8];
    const float* anony_emb = (const float*)d_in[9];
    const float* time_w    = (const float*)d_in[10];
    const float* time_b    = (const float*)d_in[11];
    const float* in_proj_w = (const float*)d_in[12];
    const float* in_proj_b = (const float*)d_in[13];
    const float* out_proj_w= (const float*)d_in[14];
    const float* out_proj_b= (const float*)d_in[15];
    const float* outfn_w   = (const float*)d_in[16];
    const float* outfn_b   = (const float*)d_in[17];
    const float* attn_wq   = (const float*)d_in[18];
    const float* attn_wk   = (const float*)d_in[19];
    const float* attn_wv   = (const float*)d_in[20];
    const float* merge_w   = (const float*)d_in[21];
    const float* merge_b   = (const float*)d_in[22];
    const float* gru_w_ih  = (const float*)d_in[23];
    const float* gru_w_hh  = (const float*)d_in[24];
    const float* gru_b_ih  = (const float*)d_in[25];
    const float* gru_b_hh  = (const float*)d_in[26];
    const float* ode_w     = (const float*)d_in[27];
    const float* ode_b     = (const float*)d_in[28];
    const float* tnode_w   = (const float*)d_in[29];
    const float* tnode_b   = (const float*)d_in[30];
    float* out = (float*)d_out;

    float *p_last, *p_wctx, *p_ctx, *p_qh, *p_qh2, *p_wnb, *p_mrg, *p_hpl,
          *p_gi, *p_gh, *p_hpr, *p_q0, *p_q2, *p_Wqt, *p_T2, *p_Gt, *p_bqh, *p_W2;
    cudaGetSymbolAddress((void**)&p_last, g_last);
    cudaGetSymbolAddress((void**)&p_wctx, g_wctx);
    cudaGetSymbolAddress((void**)&p_ctx,  g_ctx);
    cudaGetSymbolAddress((void**)&p_qh,   g_qh);
    cudaGetSymbolAddress((void**)&p_qh2,  g_qh2);
    cudaGetSymbolAddress((void**)&p_wnb,  g_wnb);
    cudaGetSymbolAddress((void**)&p_mrg,  g_mrg);
    cudaGetSymbolAddress((void**)&p_hpl,  g_hpl);
    cudaGetSymbolAddress((void**)&p_gi,   g_gi);
    cudaGetSymbolAddress((void**)&p_gh,   g_gh);
    cudaGetSymbolAddress((void**)&p_hpr,  g_hpr);
    cudaGetSymbolAddress((void**)&p_q0,   g_q0);
    cudaGetSymbolAddress((void**)&p_q2,   g_q2);
    cudaGetSymbolAddress((void**)&p_Wqt,  g_Wqt);
    cudaGetSymbolAddress((void**)&p_T2,   g_T2);
    cudaGetSymbolAddress((void**)&p_Gt,   g_Gt);
    cudaGetSymbolAddress((void**)&p_bqh,  g_bqh);
    cudaGetSymbolAddress((void**)&p_W2,   g_W2);

    cudaFuncSetAttribute(mha2_kernel, cudaFuncAttributeMaxDynamicSharedMemorySize, MHA2_SMEM);
    cudaFuncSetAttribute(attn2_kernel, cudaFuncAttributeMaxDynamicSharedMemorySize, ATT2_SMEM);
    cudaFuncSetAttribute(ode_kernel, cudaFuncAttributeMaxDynamicSharedMemorySize, ODE_SMEM);

    // --- weight prep (tiny) ---
    qprep1<<<1, DM>>>(in_proj_w, in_proj_b, time_b, p_q0);
    qprep2<<<2, DM>>>(in_proj_w, p_q0, p_q2);
    transWq<<<NF, NF>>>(attn_wq, p_Wqt);
    // T2 = Wq^T @ outfn_w   (128 x 640)
    gemm_tc<0,0><<<dim3(DM/128, 1), 256>>>(p_Wqt, NF, outfn_w, DM, nullptr, p_T2, DM, NF, DM, NF);
    // Gt = T2 @ out_proj_w  (128 x 640)
    gemm_tc<0,0><<<dim3(DM/128, 1), 256>>>(p_T2, DM, out_proj_w, DM, nullptr, p_Gt, DM, NF, DM, DM);
    biasqh_k<<<1, NF>>>(outfn_w, out_proj_b, outfn_b, attn_wq, p_bqh);
    packW2<<<DM, 256>>>(in_proj_w, p_W2);

    // --- main pipeline ---
    mha2_kernel<<<BS, 256, MHA2_SMEM>>>(nids, hist_nids, anon, eids, hist_ts, dirs,
                                        node_feat, edge_feat, anony_emb, time_w, time_b,
                                        p_q2, p_wctx, p_last);
    // ctx = wctx @ W2^T + bv   (4096 x 640, K=1280)
    gemm_tc<1,0><<<dim3(DM/128, BS/128), 256>>>(p_wctx, 2*DM, p_W2, 2*DM,
                                                in_proj_b + 2*DM, p_ctx, DM, BS, DM, 2*DM);
    // qh = ctx @ Gt^T + bqh    (4096 x 128, K=640)
    gemm_tc<1,0><<<dim3(NF/128, BS/128), 256>>>(p_ctx, DM, p_Gt, DM, p_bqh, p_qh, NF, BS, NF, DM);
    // qh2 = qh @ attn_wk^T     (4096 x 384, K=128)
    gemm_tc<1,0><<<dim3(NB3/128, BS/128), 256>>>(p_qh, NF, attn_wk, NF, nullptr, p_qh2, NB3, BS, NB3, NF);
    attn2_kernel<<<BS, 128, ATT2_SMEM>>>(nids, hist_nids, eids, hist_ts,
                                         node_feat, edge_feat, time_w, time_b,
                                         p_qh2, p_wnb, p_mrg);
    // ctx2 = wnb @ attn_wv -> mergein[:, 0:128]   (K=384)
    gemm_tc<0,0><<<dim3(NF/128, BS/128), 256>>>(p_wnb, NB3, attn_wv, NF, nullptr, p_mrg, 2*NF, BS, NF, NB3);
    // hpl = tanh(mergein @ merge_w + b)           (K=256)
    gemm_tc<0,1><<<dim3(NF/128, BS/128), 256>>>(p_mrg, 2*NF, merge_w, NF, merge_b, p_hpl, NF, BS, NF, 2*NF);
    // gi = last @ gru_w_ih^T + b                  (K=512)
    gemm_tc<1,0><<<dim3(3*NF/128, BS/128), 256>>>(p_last, DIN, gru_w_ih, DIN, gru_b_ih, p_gi, 3*NF, BS, 3*NF, DIN);
    // gh = hpl @ gru_w_hh^T + b                   (K=128)
    gemm_tc<1,0><<<dim3(3*NF/128, BS/128), 256>>>(p_hpl, NF, gru_w_hh, NF, gru_b_hh, p_gh, 3*NF, BS, 3*NF, NF);
    gru_kernel<<<(BS*NF + 255)/256, 256>>>(p_gi, p_gh, p_hpl, p_hpr);
    ode_kernel<<<BS, 128, ODE_SMEM>>>(p_hpr, ode_w, ode_b, tnode_w, tnode_b, hist_ts, out);
}

// round 6
// speedup vs baseline: 5.4224x; 1.0188x over previous
#include <cuda_runtime.h>
#include <math.h>
#include <stdint.h>

#define BS   4096
#define L    20
#define NF   128
#define DM   640
#define DIN  512
#define DH   320
#define NB3  384

// ---------------- scratch ----------------
__device__ float g_last [BS*DIN];
__device__ float g_wctx [BS*2*DM];
__device__ float g_qh   [BS*NF];
__device__ float g_qh2  [BS*NB3];
__device__ float g_A2   [BS*512];      // [wnb(384) | node_feat[nids](128)]
__device__ float g_hpl  [BS*NF];
__device__ float g_gi   [BS*3*NF];
__device__ float g_gh   [BS*3*NF];
__device__ float g_hpr  [BS*NF];
__device__ float g_q2   [2*DM];
__device__ float g_G3   [NF*2*DM];     // folded (attn_wq∘outfn∘out_proj∘Wv) (128 x 1280)
__device__ float g_b3   [NF];
__device__ float g_Wcmb [512*NF];      // [attn_wv@merge_w_top ; merge_w_bot]

__device__ __forceinline__ unsigned f2tf(float v) {
    unsigned r;
    asm("cvt.rna.tf32.f32 %0, %1;" : "=r"(r) : "f"(v));
    return r;
}

__device__ __forceinline__ void mma_tf32(float c[4], unsigned a0, unsigned a1,
                                         unsigned a2, unsigned a3,
                                         unsigned b0, unsigned b1) {
    asm volatile(
        "mma.sync.aligned.m16n8k8.row.col.f32.tf32.tf32.f32 "
        "{%0,%1,%2,%3}, {%4,%5,%6,%7}, {%8,%9}, {%0,%1,%2,%3};"
        : "+f"(c[0]), "+f"(c[1]), "+f"(c[2]), "+f"(c[3])
        : "r"(a0), "r"(a1), "r"(a2), "r"(a3), "r"(b0), "r"(b1));
}

// ---------------- tf32 mma.sync GEMM, double-buffered ----------------
template<int BT, int ACT>
__global__ __launch_bounds__(256, 2) void gemm_tc(
    const float* __restrict__ A, int lda,
    const float* __restrict__ B, int ldb,
    const float* __restrict__ bias,
    float* __restrict__ C, int ldc,
    int M, int N, int K)
{
    __shared__ __align__(16) unsigned As[2*2048];
    __shared__ __align__(16) unsigned Bs[2*2048];
    const int bm = blockIdx.y * 128;
    const int bn = blockIdx.x * 128;
    const int t  = threadIdx.x;
    const int lane = t & 31;
    const int wr = (t >> 5) >> 2;
    const int wc = (t >> 5) & 3;

    const int ma = t >> 2, ca = t & 3;
    const float* Ag = A + (size_t)(bm + ma) * lda + ca * 4;
    const float* Bg;
    int kb = 0, nb4 = 0, nbr = 0, cb = 0;
    if (BT) { nbr = t >> 2; cb = t & 3; Bg = B + (size_t)(bn + nbr) * ldb + cb * 4; }
    else    { kb = t >> 5; nb4 = t & 31; Bg = B + (size_t)kb * ldb + bn + nb4 * 4; }

    float4 ra0, ra1, rb0, rb1;
    auto ldg = [&]() {
        ra0 = *(const float4*)Ag;
        ra1 = *(const float4*)(Ag + (size_t)64 * lda);
        Ag += 16;
        if (BT) {
            rb0 = *(const float4*)Bg;
            rb1 = *(const float4*)(Bg + (size_t)64 * ldb);
            Bg += 16;
        } else {
            rb0 = *(const float4*)Bg;
            rb1 = *(const float4*)(Bg + (size_t)8 * ldb);
            Bg += (size_t)16 * ldb;
        }
    };

    const int imA = ma >> 4, rA = ma & 15, gA = rA & 7, hiA = rA >> 3;
    const int sA = ca >> 1, k2A = ca & 1;
    const int baseA0 = (((sA * 8 + imA)     * 32 + gA * 4) * 4) + k2A * 2 + hiA;
    const int baseA1 = (((sA * 8 + imA + 4) * 32 + gA * 4) * 4) + k2A * 2 + hiA;

    auto sts = [&](int buf) {
        unsigned* Ab = As + buf * 2048;
        unsigned* Bb = Bs + buf * 2048;
        const float* v0 = &ra0.x; const float* v1 = &ra1.x;
        #pragma unroll
        for (int j = 0; j < 4; j++) {
            Ab[baseA0 + 4*j] = f2tf(v0[j]);
            Ab[baseA1 + 4*j] = f2tf(v1[j]);
        }
        if (BT) {
            const int g = nbr & 7, jn0 = (nbr >> 3), jn1 = jn0 + 8;
            const int sB = cb >> 1, regB = cb & 1;
            const int b0 = ((sB * 16 + jn0) * 32 + g * 4) * 2 + regB;
            const int b1 = ((sB * 16 + jn1) * 32 + g * 4) * 2 + regB;
            const float* w0 = &rb0.x; const float* w1 = &rb1.x;
            #pragma unroll
            for (int j = 0; j < 4; j++) {
                Bb[b0 + 2*j] = f2tf(w0[j]);
                Bb[b1 + 2*j] = f2tf(w1[j]);
            }
        } else {
            const int jn = nb4 >> 1, gb = (nb4 & 1) * 4;
            const int tig = kb & 3, regB = (kb >> 2) & 1;
            const int b0 = ((0 * 16 + jn) * 32 + gb * 4 + tig) * 2 + regB;
            const int b1 = ((1 * 16 + jn) * 32 + gb * 4 + tig) * 2 + regB;
            const float* w0 = &rb0.x; const float* w1 = &rb1.x;
            #pragma unroll
            for (int j = 0; j < 4; j++) {
                Bb[b0 + 8*j] = f2tf(w0[j]);
                Bb[b1 + 8*j] = f2tf(w1[j]);
            }
        }
    };

    float acc[4][4][4] = {};
    auto domma = [&](int buf) {
        const unsigned* Ab = As + buf * 2048;
        const unsigned* Bb = Bs + buf * 2048;
        #pragma unroll
        for (int s = 0; s < 2; s++) {
            uint4 af[4]; uint2 bf[4];
            #pragma unroll
            for (int i = 0; i < 4; i++)
                af[i] = *(const uint4*)&Ab[((s*8 + wr*4 + i) * 32 + lane) * 4];
            #pragma unroll
            for (int j = 0; j < 4; j++)
                bf[j] = *(const uint2*)&Bb[((s*16 + wc*4 + j) * 32 + lane) * 2];
            #pragma unroll
            for (int i = 0; i < 4; i++)
                #pragma unroll
                for (int j = 0; j < 4; j++)
                    mma_tf32(acc[i][j], af[i].x, af[i].y, af[i].z, af[i].w,
                             bf[j].x, bf[j].y);
        }
    };

    const int niter = K >> 4;
    ldg();
    sts(0);
    if (niter > 1) ldg();
    __syncthreads();
    for (int it = 0; it < niter; it++) {
        domma(it & 1);
        if (it + 1 < niter) {
            sts((it + 1) & 1);
            if (it + 2 < niter) ldg();
        }
        __syncthreads();
    }

    const int g = lane >> 2, tig = lane & 3;
    #pragma unroll
    for (int i = 0; i < 4; i++) {
        int row = bm + wr * 64 + i * 16 + g;
        #pragma unroll
        for (int j = 0; j < 4; j++) {
            int col = bn + wc * 32 + j * 8 + tig * 2;
            float b0 = bias ? bias[col] : 0.f;
            float b1 = bias ? bias[col + 1] : 0.f;
            float v00 = acc[i][j][0] + b0, v01 = acc[i][j][1] + b1;
            float v10 = acc[i][j][2] + b0, v11 = acc[i][j][3] + b1;
            if (ACT == 1) { v00 = tanhf(v00); v01 = tanhf(v01);
                            v10 = tanhf(v10); v11 = tanhf(v11); }
            *(float2*)(C + (size_t)row * ldc + col)       = make_float2(v00, v01);
            *(float2*)(C + (size_t)(row + 8) * ldc + col) = make_float2(v10, v11);
        }
    }
}

// ---------------- prep_q: q2 per head (block h in {0,1}, 640 threads) ----------------
__global__ void prep_q(const float* __restrict__ ipw, const float* __restrict__ ipb,
                       const float* __restrict__ time_b, float* __restrict__ q2)
{
    __shared__ float tc[NF];
    __shared__ float q0s[DH];
    int h = blockIdx.x, t = threadIdx.x;
    if (t < NF) tc[t] = cosf(time_b[t]);
    __syncthreads();
    if (t < DH) {
        int e = h*DH + t;
        float acc = ipb[e];
        const float* row = ipw + (size_t)e * DM + DIN;
        for (int k = 0; k < NF; k++) acc += tc[k] * row[k];
        q0s[t] = acc;
    }
    __syncthreads();
    float acc = 0.f;
    const float* base = ipw + (size_t)(DM + h*DH) * DM + t;
    for (int d = 0; d < DH; d++) acc += q0s[d] * base[(size_t)d * DM];
    q2[h*DM + t] = acc;
}

// ---------------- prep_G: G3 rows, b3, Wcmb (grid 640, 256 threads) ----------------
__global__ __launch_bounds__(256) void prep_G(
    const float* __restrict__ ipw, const float* __restrict__ ipb,
    const float* __restrict__ opw, const float* __restrict__ opb,
    const float* __restrict__ wf, const float* __restrict__ bf,
    const float* __restrict__ wq, const float* __restrict__ wv,
    const float* __restrict__ mw,
    float* __restrict__ G3, float* __restrict__ b3, float* __restrict__ Wcmb)
{
    int i = blockIdx.x, t = threadIdx.x;
    if (i >= 128) {
        int r = i - 128;
        if (r < 384) {            // M5 row: attn_wv @ merge_w_top
            if (t < NF) {
                float acc = 0.f;
                const float* wvr = wv + (size_t)r * NF;
                for (int k = 0; k < NF; k++) acc += wvr[k] * mw[k * NF + t];
                Wcmb[(size_t)r * NF + t] = acc;
            }
        } else {                  // copy merge_w bottom
            int r2 = r - 384;
            if (t < NF) Wcmb[(size_t)(384 + r2) * NF + t] = mw[(NF + r2) * NF + t];
        }
        return;
    }
    __shared__ float wqc[NF];
    __shared__ float b1s[NF];
    __shared__ float t2[DM];
    __shared__ float gt[DM];
    __shared__ float red[256];
    if (t < NF) {
        wqc[t] = wq[t * NF + i];
        float acc = bf[t];
        const float* row = wf + (size_t)t * DM;
        for (int m = 0; m < DM; m++) acc += row[m] * opb[m];
        b1s[t] = acc;
    }
    __syncthreads();
    for (int j = t; j < DM; j += 256) {
        float acc = 0.f;
        for (int q = 0; q < NF; q++) acc += wqc[q] * wf[(size_t)q * DM + j];
        t2[j] = acc;
    }
    __syncthreads();
    for (int d = t; d < DM; d += 256) {
        float acc = 0.f;
        for (int m = 0; m < DM; m++) acc += t2[m] * opw[(size_t)m * DM + d];
        gt[d] = acc;
    }
    __syncthreads();
    for (int c = t; c < 2*DM; c += 256) {
        int h = c / DM, cc = c - h*DM;
        float acc = 0.f;
        const float* base = ipw + (size_t)(2*DM + h*DH) * DM + cc;
        const float* gth = gt + h*DH;
        for (int dd = 0; dd < DH; dd++) acc += gth[dd] * base[(size_t)dd * DM];
        G3[(size_t)i * (2*DM) + c] = acc;
    }
    // b3[i] = gt . bv + b1s . wqc
    float p = 0.f;
    for (int d = t; d < DM; d += 256) p += gt[d] * ipb[2*DM + d];
    if (t < NF) p += b1s[t] * wqc[t];
    red[t] = p;
    __syncthreads();
    if (t == 0) {
        float s = 0.f;
        for (int k = 0; k < 256; k++) s += red[k];
        b3[i] = s;
    }
}

// ---------------- MHA stage ----------------
#define MHA2_SMEM ((L*DM + 2*DM + 64) * 4 + L*5*4)
__global__ __launch_bounds__(256) void mha2_kernel(
    const int* __restrict__ nids, const int* __restrict__ hist_nids,
    const int* __restrict__ anon_ids, const int* __restrict__ hist_eids,
    const float* __restrict__ hist_ts, const int* __restrict__ hist_dirs,
    const float* __restrict__ node_feat, const float* __restrict__ edge_feat,
    const float* __restrict__ anony_emb, const float* __restrict__ time_w,
    const float* __restrict__ time_b, const float* __restrict__ q2,
    float* __restrict__ wctx, float* __restrict__ last)
{
    extern __shared__ float sm[];
    float* rows = sm;
    float* q2s  = sm + L*DM;
    float* sc   = q2s + 2*DM;
    int*   hn   = (int*)(sc + 64);
    int*   eid  = hn + L;
    int*   aid  = eid + L;
    int*   dirr = aid + L;
    float* dts  = (float*)(dirr + L);

    int b = blockIdx.x, t = threadIdx.x;
    if (t < L) {
        hn[t]  = hist_nids[b*L + t];
        eid[t] = hist_eids[b*L + t];
        aid[t] = anon_ids[b*L + t];
        dirr[t] = hist_dirs[b*L + t];
        dts[t] = hist_ts[b*L + L-1] - hist_ts[b*L + t];
    }
    for (int i = t; i < 2*DM; i += 256) q2s[i] = q2[i];
    __syncthreads();
    int nid = nids[b];

    for (int idx = t; idx < L*DM; idx += 256) {
        int m = idx / DM, d = idx - m*DM;
        float v;
        if (d < NF) {
            int src = dirr[m] ? nid : hn[m];
            v = node_feat[(size_t)src*NF + d];
        } else if (d < 2*NF) {
            int dst = dirr[m] ? hn[m] : nid;
            v = node_feat[(size_t)dst*NF + (d - NF)];
        } else if (d < 3*NF) {
            v = anony_emb[(size_t)aid[m]*NF + (d - 2*NF)];
        } else if (d < 4*NF) {
            v = edge_feat[(size_t)eid[m]*NF + (d - 3*NF)];
        } else {
            int f = d - 4*NF;
            v = cosf(fmaf(dts[m], time_w[f], time_b[f]));
        }
        if (m == L-1 && d < DIN) {
            last[(size_t)b*DIN + d] = v;
            v = 0.f;
        }
        rows[idx] = v;
    }
    __syncthreads();

    int w = t >> 5, lane = t & 31;
    for (int p = w; p < 2*L; p += 8) {
        int h = p / L, m = p - h*L;
        const float* qp = q2s + h*DM;
        const float* rp = rows + m*DM;
        float s = 0.f;
        for (int d = lane; d < DM; d += 32) s += qp[d] * rp[d];
        #pragma unroll
        for (int o = 16; o; o >>= 1) s += __shfl_xor_sync(0xffffffffu, s, o);
        if (lane == 0) {
            bool msk = (hn[m] == 0) && (m != L-1);
            sc[h*L + m] = msk ? -1e9f : s * (1.f / sqrtf((float)DH));
        }
    }
    __syncthreads();
    if (t < 2) {
        float mx = -1e30f;
        for (int m = 0; m < L; m++) mx = fmaxf(mx, sc[t*L + m]);
        float sum = 0.f;
        for (int m = 0; m < L; m++) { float e = expf(sc[t*L + m] - mx); sc[t*L + m] = e; sum += e; }
        float inv = 1.f / sum;
        for (int m = 0; m < L; m++) sc[t*L + m] *= inv;
    }
    __syncthreads();
    for (int i = t; i < 2*DM; i += 256) {
        int h = i / DM, d = i - h*DM;
        float acc = 0.f;
        #pragma unroll
        for (int m = 0; m < L; m++) acc += sc[h*L + m] * rows[m*DM + d];
        wctx[(size_t)b*(2*DM) + i] = acc;
    }
}

// ---------------- pooling attention stage ----------------
#define ATT2_SMEM ((L*NB3 + NB3 + 32) * 4 + L*3*4)
__global__ __launch_bounds__(128) void attn2_kernel(
    const int* __restrict__ nids, const int* __restrict__ hist_nids,
    const int* __restrict__ hist_eids, const float* __restrict__ hist_ts,
    const float* __restrict__ node_feat, const float* __restrict__ edge_feat,
    const float* __restrict__ time_w, const float* __restrict__ time_b,
    const float* __restrict__ qh2,
    float* __restrict__ A2)
{
    extern __shared__ float sm[];
    float* rows = sm;
    float* qs   = sm + L*NB3;
    float* a    = qs + NB3;
    int*   hn   = (int*)(a + 32);
    int*   eid  = hn + L;
    float* dts  = (float*)(eid + L);

    int b = blockIdx.x, t = threadIdx.x;
    if (t < L) {
        hn[t]  = hist_nids[b*L + t];
        eid[t] = hist_eids[b*L + t];
        dts[t] = hist_ts[b*L + L-1] - hist_ts[b*L + t];
    }
    for (int i = t; i < NB3; i += 128) qs[i] = qh2[(size_t)b*NB3 + i];
    __syncthreads();

    for (int idx = t; idx < L*NB3; idx += 128) {
        int m = idx / NB3, d = idx - m*NB3;
        float v;
        if (d < NF)          v = node_feat[(size_t)hn[m]*NF + d];
        else if (d < 2*NF)   v = edge_feat[(size_t)eid[m]*NF + (d - NF)];
        else {
            int f = d - 2*NF;
            v = cosf(fmaf(dts[m], time_w[f], time_b[f]));
        }
        rows[idx] = v;
    }
    __syncthreads();

    int w = t >> 5, lane = t & 31;
    for (int l = w; l < L; l += 4) {
        const float* rp = rows + l*NB3;
        float s = 0.f;
        for (int d = lane; d < NB3; d += 32) s += qs[d] * rp[d];
        #pragma unroll
        for (int o = 16; o; o >>= 1) s += __shfl_xor_sync(0xffffffffu, s, o);
        if (lane == 0) {
            bool msk = (hn[l] == 0) && (l != L-1);
            a[l] = msk ? -1e9f : s * (1.f / sqrtf((float)NF));
        }
    }
    __syncthreads();
    if (t == 0) {
        float mx = -1e30f;
        for (int l = 0; l < L; l++) mx = fmaxf(mx, a[l]);
        float sum = 0.f;
        for (int l = 0; l < L; l++) { float e = expf(a[l] - mx); a[l] = e; sum += e; }
        float inv = 1.f / sum;
        for (int l = 0; l < L; l++) a[l] *= inv;
    }
    __syncthreads();
    for (int d = t; d < NB3; d += 128) {
        float acc = 0.f;
        #pragma unroll
        for (int l = 0; l < L; l++) acc += a[l] * rows[l*NB3 + d];
        A2[(size_t)b*512 + d] = acc;
    }
    A2[(size_t)b*512 + NB3 + t] = node_feat[(size_t)nids[b]*NF + t];
}

// ---------------- GRU ----------------
__global__ void gru_kernel(const float* __restrict__ gi, const float* __restrict__ gh,
                           const float* __restrict__ hpl, float* __restrict__ hpr)
{
    int idx = blockIdx.x * blockDim.x + threadIdx.x;
    if (idx >= BS*NF) return;
    int b = idx / NF, f = idx - b*NF;
    const float* gib = gi + (size_t)b*3*NF;
    const float* ghb = gh + (size_t)b*3*NF;
    float r = 1.f / (1.f + expf(-(gib[f]      + ghb[f])));
    float z = 1.f / (1.f + expf(-(gib[NF + f] + ghb[NF + f])));
    float n = tanhf(gib[2*NF + f] + r * ghb[2*NF + f]);
    hpr[idx] = (1.f - z) * n + z * hpl[idx];
}

// ---------------- RK4 ODE ----------------
#define ODE_SMEM ((128*129 + 128) * 4)
__global__ __launch_bounds__(128) void ode_kernel(
    const float* __restrict__ hpr, const float* __restrict__ ode_w,
    const float* __restrict__ ode_b, const float* __restrict__ tnode_w,
    const float* __restrict__ tnode_b, const float* __restrict__ hist_ts,
    float* __restrict__ out)
{
    extern __shared__ float sm[];
    float* Wsm = sm;
    float* vs  = sm + 128*129;
    int b = blockIdx.x, f = threadIdx.x;
    for (int i = f; i < NF*NF; i += 128) Wsm[(i >> 7)*129 + (i & 127)] = ode_w[i];
    float t0 = hist_ts[b*L + L-2];
    float t1 = hist_ts[b*L + L-1];
    float ratio = t1 - t0;
    float twf = tnode_w[f], tbf = tnode_b[f], obf = ode_b[f];
    float h0 = hpr[(size_t)b*NF + f];
    float z = h0;
    __syncthreads();
    float w[NF];
    #pragma unroll
    for (int k = 0; k < NF; k++) w[k] = Wsm[f*129 + k];
    __syncthreads();

    auto feval = [&](float s, float zin) -> float {
        float t = fmaf(s, ratio, t0);
        vs[f] = zin + cosf(fmaf(t, twf, tbf));
        __syncthreads();
        float acc = obf;
        #pragma unroll
        for (int k = 0; k < NF; k += 4) {
            float4 v = *(const float4*)&vs[k];
            acc += v.x * w[k] + v.y * w[k+1] + v.z * w[k+2] + v.w * w[k+3];
        }
        __syncthreads();
        return tanhf(acc) * ratio;
    };

    const float ds = 0.125f;
    for (int st = 0; st < 8; st++) {
        float s = st * ds;
        float k1 = feval(s,            z);
        float k2 = feval(s + 0.5f*ds,  z + 0.5f*ds*k1);
        float k3 = feval(s + 0.5f*ds,  z + 0.5f*ds*k2);
        float k4 = feval(s + ds,       z + ds*k3);
        z += ds * (1.f/6.f) * (k1 + 2.f*k2 + 2.f*k3 + k4);
    }
    out[(size_t)b*NF + f] = z;
    out[(size_t)BS*NF + (size_t)b*NF + f] = h0;
    if (f == 0) out[(size_t)2*BS*NF + b] = t1;
}

// ---------------- launch ----------------
extern "C" void kernel_launch(void* const* d_in, const int* in_sizes, int n_in,
                              void* d_out, int out_size)
{
    const int*   nids      = (const int*)  d_in[0];
    const int*   hist_nids = (const int*)  d_in[2];
    const int*   anon      = (const int*)  d_in[3];
    const int*   eids      = (const int*)  d_in[4];
    const float* hist_ts   = (const float*)d_in[5];
    const int*   dirs      = (const int*)  d_in[6];
    const float* node_feat = (const float*)d_in[7];
    const float* edge_feat = (const float*)d_in[8];
    const float* anony_emb = (const float*)d_in[9];
    const float* time_w    = (const float*)d_in[10];
    const float* time_b    = (const float*)d_in[11];
    const float* in_proj_w = (const float*)d_in[12];
    const float* in_proj_b = (const float*)d_in[13];
    const float* out_proj_w= (const float*)d_in[14];
    const float* out_proj_b= (const float*)d_in[15];
    const float* outfn_w   = (const float*)d_in[16];
    const float* outfn_b   = (const float*)d_in[17];
    const float* attn_wq   = (const float*)d_in[18];
    const float* attn_wk   = (const float*)d_in[19];
    const float* attn_wv   = (const float*)d_in[20];
    const float* merge_w   = (const float*)d_in[21];
    const float* merge_b   = (const float*)d_in[22];
    const float* gru_w_ih  = (const float*)d_in[23];
    const float* gru_w_hh  = (const float*)d_in[24];
    const float* gru_b_ih  = (const float*)d_in[25];
    const float* gru_b_hh  = (const float*)d_in[26];
    const float* ode_w     = (const float*)d_in[27];
    const float* ode_b     = (const float*)d_in[28];
    const float* tnode_w   = (const float*)d_in[29];
    const float* tnode_b   = (const float*)d_in[30];
    float* out = (float*)d_out;

    float *p_last, *p_wctx, *p_qh, *p_qh2, *p_A2, *p_hpl, *p_gi, *p_gh, *p_hpr,
          *p_q2, *p_G3, *p_b3, *p_Wcmb;
    cudaGetSymbolAddress((void**)&p_last, g_last);
    cudaGetSymbolAddress((void**)&p_wctx, g_wctx);
    cudaGetSymbolAddress((void**)&p_qh,   g_qh);
    cudaGetSymbolAddress((void**)&p_qh2,  g_qh2);
    cudaGetSymbolAddress((void**)&p_A2,   g_A2);
    cudaGetSymbolAddress((void**)&p_hpl,  g_hpl);
    cudaGetSymbolAddress((void**)&p_gi,   g_gi);
    cudaGetSymbolAddress((void**)&p_gh,   g_gh);
    cudaGetSymbolAddress((void**)&p_hpr,  g_hpr);
    cudaGetSymbolAddress((void**)&p_q2,   g_q2);
    cudaGetSymbolAddress((void**)&p_G3,   g_G3);
    cudaGetSymbolAddress((void**)&p_b3,   g_b3);
    cudaGetSymbolAddress((void**)&p_Wcmb, g_Wcmb);

    cudaFuncSetAttribute(mha2_kernel, cudaFuncAttributeMaxDynamicSharedMemorySize, MHA2_SMEM);
    cudaFuncSetAttribute(attn2_kernel, cudaFuncAttributeMaxDynamicSharedMemorySize, ATT2_SMEM);
    cudaFuncSetAttribute(ode_kernel, cudaFuncAttributeMaxDynamicSharedMemorySize, ODE_SMEM);

    // --- prep (2 kernels, ~15us) ---
    prep_q<<<2, DM>>>(in_proj_w, in_proj_b, time_b, p_q2);
    prep_G<<<640, 256>>>(in_proj_w, in_proj_b, out_proj_w, out_proj_b,
                         outfn_w, outfn_b, attn_wq, attn_wv, merge_w,
                         p_G3, p_b3, p_Wcmb);

    // --- main pipeline ---
    mha2_kernel<<<BS, 256, MHA2_SMEM>>>(nids, hist_nids, anon, eids, hist_ts, dirs,
                                        node_feat, edge_feat, anony_emb, time_w, time_b,
                                        p_q2, p_wctx, p_last);
    // qh = wctx @ G3^T + b3   (4096 x 128, K=1280)
    gemm_tc<1,0><<<dim3(1, BS/128), 256>>>(p_wctx, 2*DM, p_G3, 2*DM, p_b3,
                                           p_qh, NF, BS, NF, 2*DM);
    // qh2 = qh @ attn_wk^T    (4096 x 384, K=128)
    gemm_tc<1,0><<<dim3(NB3/128, BS/128), 256>>>(p_qh, NF, attn_wk, NF, nullptr,
                                                 p_qh2, NB3, BS, NB3, NF);
    attn2_kernel<<<BS, 128, ATT2_SMEM>>>(nids, hist_nids, eids, hist_ts,
                                         node_feat, edge_feat, time_w, time_b,
                                         p_qh2, p_A2);
    // hpl = tanh(A2 @ Wcmb + merge_b)   (4096 x 128, K=512)
    gemm_tc<0,1><<<dim3(1, BS/128), 256>>>(p_A2, 512, p_Wcmb, NF, merge_b,
                                           p_hpl, NF, BS, NF, 512);
    // gi = last @ gru_w_ih^T + b        (K=512)
    gemm_tc<1,0><<<dim3(3*NF/128, BS/128), 256>>>(p_last, DIN, gru_w_ih, DIN, gru_b_ih,
                                                  p_gi, 3*NF, BS, 3*NF, DIN);
    // gh = hpl @ gru_w_hh^T + b         (K=128)
    gemm_tc<1,0><<<dim3(3*NF/128, BS/128), 256>>>(p_hpl, NF, gru_w_hh, NF, gru_b_hh,
                                                  p_gh, 3*NF, BS, 3*NF, NF);
    gru_kernel<<<(BS*NF + 255)/256, 256>>>(p_gi, p_gh, p_hpl, p_hpr);
    ode_kernel<<<BS, 128, ODE_SMEM>>>(p_hpr, ode_w, ode_b, tnode_w, tnode_b, hist_ts, out);
}